// round 2
// baseline (speedup 1.0000x reference)
#include <cuda_runtime.h>
#include <math.h>

#define T_LEN 2048
#define BSZ   2
#define DMODEL 1024
#define NH    16
#define HDIM  64
#define EMB   1024           // NH*HDIM
#define MROWS 4096           // T_LEN*BSZ

typedef unsigned long long ull;

// ---------------- packed f32x2 helpers (sm_100+ PTX) ------------------------
__device__ __forceinline__ ull pack2(float a, float b) {
    ull r;
    asm("mov.b64 %0, {%1, %2};" : "=l"(r) : "f"(a), "f"(b));
    return r;
}
__device__ __forceinline__ void unpack2(ull v, float& a, float& b) {
    asm("mov.b64 {%0, %1}, %2;" : "=f"(a), "=f"(b) : "l"(v));
}
__device__ __forceinline__ ull fma2(ull a, ull b, ull c) {
    ull d;
    asm("fma.rn.f32x2 %0, %1, %2, %3;" : "=l"(d) : "l"(a), "l"(b), "l"(c));
    return d;
}
__device__ __forceinline__ ull mul2(ull a, ull b) {
    ull d;
    asm("mul.rn.f32x2 %0, %1, %2;" : "=l"(d) : "l"(a), "l"(b));
    return d;
}
__device__ __forceinline__ ull add2(ull a, ull b) {
    ull d;
    asm("add.rn.f32x2 %0, %1, %2;" : "=l"(d) : "l"(a), "l"(b));
    return d;
}

// ---------------- scratch (allocation-free: device globals) ----------------
__device__ float g_q[(size_t)BSZ * NH * T_LEN * HDIM];   // [b][h][t][d]
__device__ float g_k[(size_t)BSZ * NH * T_LEN * HDIM];
__device__ float g_v[(size_t)BSZ * NH * T_LEN * HDIM];
__device__ float g_attn[(size_t)MROWS * EMB];            // [t*B+b][e]

// ============================================================================
// GEMM (TN): C[M,N] = A[M,K] @ W[N,K]^T (+bias). BM=BN=128, BK=16, 256 thr,
// 8x8 per thread, inner product in packed f32x2 (acc2[8][4]).
// ============================================================================
#define BM 128
#define BN 128
#define BK 16
#define SPAD 4

// -------- QKV projection: z selects q/k/v; scatters to [b][h][t][d] --------
__global__ __launch_bounds__(256) void qkv_gemm(
    const float* __restrict__ Xq, const float* __restrict__ Xk,
    const float* __restrict__ Xv, const float* __restrict__ W,
    const float* __restrict__ bias)
{
    const int z = blockIdx.z;
    const float* A  = (z == 0) ? Xq : (z == 1) ? Xk : Xv;
    const float* Wz = W + (size_t)z * EMB * DMODEL;
    const float* bz = bias + (size_t)z * EMB;
    float* dst = (z == 0) ? g_q : (z == 1) ? g_k : g_v;

    __shared__ float As[BK][BM + SPAD];
    __shared__ float Ws[BK][BN + SPAD];

    const int tid = threadIdx.x;
    const int tx = tid & 15;          // N direction (16)
    const int ty = tid >> 4;          // M direction (16)
    const int m0 = blockIdx.y * BM;
    const int n0 = blockIdx.x * BN;

    ull acc2[8][4];
    #pragma unroll
    for (int i = 0; i < 8; i++)
        #pragma unroll
        for (int j = 0; j < 4; j++) acc2[i][j] = 0ull;

    for (int k0 = 0; k0 < DMODEL; k0 += BK) {
        #pragma unroll
        for (int it = 0; it < 2; it++) {
            int idx = tid + it * 256;        // 0..511
            int row = idx >> 2;              // 0..127
            int c4  = (idx & 3) << 2;        // 0,4,8,12
            float4 a = *(const float4*)(A  + (size_t)(m0 + row) * DMODEL + k0 + c4);
            As[c4 + 0][row] = a.x; As[c4 + 1][row] = a.y;
            As[c4 + 2][row] = a.z; As[c4 + 3][row] = a.w;
            float4 w = *(const float4*)(Wz + (size_t)(n0 + row) * DMODEL + k0 + c4);
            Ws[c4 + 0][row] = w.x; Ws[c4 + 1][row] = w.y;
            Ws[c4 + 2][row] = w.z; Ws[c4 + 3][row] = w.w;
        }
        __syncthreads();
        #pragma unroll
        for (int k = 0; k < BK; k++) {
            float af[8];
            *(float4*)&af[0] = *(const float4*)&As[k][ty * 8];
            *(float4*)&af[4] = *(const float4*)&As[k][ty * 8 + 4];
            ulonglong2 w01 = *(const ulonglong2*)&Ws[k][tx * 8];
            ulonglong2 w23 = *(const ulonglong2*)&Ws[k][tx * 8 + 4];
            ull wf2[4];
            wf2[0] = w01.x; wf2[1] = w01.y; wf2[2] = w23.x; wf2[3] = w23.y;
            #pragma unroll
            for (int i = 0; i < 8; i++) {
                ull a2 = pack2(af[i], af[i]);
                #pragma unroll
                for (int j = 0; j < 4; j++)
                    acc2[i][j] = fma2(a2, wf2[j], acc2[i][j]);
            }
        }
        __syncthreads();
    }

    const float scale = (z == 0) ? 0.125f : 1.0f;   // HD^-0.5 = 64^-0.5
    #pragma unroll
    for (int i = 0; i < 8; i++) {
        int m = m0 + ty * 8 + i;
        int t = m >> 1;           // B=2
        int b = m & 1;
        #pragma unroll
        for (int jj = 0; jj < 2; jj++) {            // two float4 chunks
            int n = n0 + tx * 8 + jj * 4;
            int h = n >> 6;       // /HDIM
            int d = n & 63;
            float c0, c1, c2, c3;
            unpack2(acc2[i][jj * 2 + 0], c0, c1);
            unpack2(acc2[i][jj * 2 + 1], c2, c3);
            float4 r;
            r.x = (c0 + __ldg(&bz[n + 0])) * scale;
            r.y = (c1 + __ldg(&bz[n + 1])) * scale;
            r.z = (c2 + __ldg(&bz[n + 2])) * scale;
            r.w = (c3 + __ldg(&bz[n + 3])) * scale;
            *(float4*)(dst + (((size_t)(b * NH + h) * T_LEN + t) * HDIM + d)) = r;
        }
    }
}

// -------- Output projection: C = g_attn @ Wo^T + bo, plain layout ----------
__global__ __launch_bounds__(256) void out_gemm(
    const float* __restrict__ W, const float* __restrict__ bias,
    float* __restrict__ C)
{
    const float* A = g_attn;

    __shared__ float As[BK][BM + SPAD];
    __shared__ float Ws[BK][BN + SPAD];

    const int tid = threadIdx.x;
    const int tx = tid & 15;
    const int ty = tid >> 4;
    const int m0 = blockIdx.y * BM;
    const int n0 = blockIdx.x * BN;

    ull acc2[8][4];
    #pragma unroll
    for (int i = 0; i < 8; i++)
        #pragma unroll
        for (int j = 0; j < 4; j++) acc2[i][j] = 0ull;

    for (int k0 = 0; k0 < EMB; k0 += BK) {
        #pragma unroll
        for (int it = 0; it < 2; it++) {
            int idx = tid + it * 256;
            int row = idx >> 2;
            int c4  = (idx & 3) << 2;
            float4 a = *(const float4*)(A + (size_t)(m0 + row) * EMB + k0 + c4);
            As[c4 + 0][row] = a.x; As[c4 + 1][row] = a.y;
            As[c4 + 2][row] = a.z; As[c4 + 3][row] = a.w;
            float4 w = *(const float4*)(W + (size_t)(n0 + row) * EMB + k0 + c4);
            Ws[c4 + 0][row] = w.x; Ws[c4 + 1][row] = w.y;
            Ws[c4 + 2][row] = w.z; Ws[c4 + 3][row] = w.w;
        }
        __syncthreads();
        #pragma unroll
        for (int k = 0; k < BK; k++) {
            float af[8];
            *(float4*)&af[0] = *(const float4*)&As[k][ty * 8];
            *(float4*)&af[4] = *(const float4*)&As[k][ty * 8 + 4];
            ulonglong2 w01 = *(const ulonglong2*)&Ws[k][tx * 8];
            ulonglong2 w23 = *(const ulonglong2*)&Ws[k][tx * 8 + 4];
            ull wf2[4];
            wf2[0] = w01.x; wf2[1] = w01.y; wf2[2] = w23.x; wf2[3] = w23.y;
            #pragma unroll
            for (int i = 0; i < 8; i++) {
                ull a2 = pack2(af[i], af[i]);
                #pragma unroll
                for (int j = 0; j < 4; j++)
                    acc2[i][j] = fma2(a2, wf2[j], acc2[i][j]);
            }
        }
        __syncthreads();
    }

    #pragma unroll
    for (int i = 0; i < 8; i++) {
        int m = m0 + ty * 8 + i;
        #pragma unroll
        for (int jj = 0; jj < 2; jj++) {
            int n = n0 + tx * 8 + jj * 4;
            float c0, c1, c2, c3;
            unpack2(acc2[i][jj * 2 + 0], c0, c1);
            unpack2(acc2[i][jj * 2 + 1], c2, c3);
            float4 r;
            r.x = c0 + __ldg(&bias[n + 0]);
            r.y = c1 + __ldg(&bias[n + 1]);
            r.z = c2 + __ldg(&bias[n + 2]);
            r.w = c3 + __ldg(&bias[n + 3]);
            *(float4*)(C + (size_t)m * DMODEL + n) = r;
        }
    }
}

// ============================================================================
// Flash attention, packed f32x2: one CTA = (128 query rows, one (b,h)).
// q + O accumulators as 32 packed f32-pairs each; K/V 64x64 tiles in smem
// (broadcast 128-bit reads); online softmax in groups of 16 keys.
// ============================================================================
__global__ __launch_bounds__(128) void flash_attn(const float* __restrict__ mask,
                                                  float* __restrict__ attn_out)
{
    __shared__ float Ks[64 * 64];
    __shared__ float Vs[64 * 64];

    const int bh = blockIdx.y;                       // b*NH + h
    const int t  = blockIdx.x * 128 + threadIdx.x;   // global query row

    const float* qp = g_q + ((size_t)bh * T_LEN + t) * HDIM;
    ull q2[32];
    #pragma unroll
    for (int i = 0; i < 32; i += 2) {
        ulonglong2 v = *(const ulonglong2*)(qp + 2 * i);
        q2[i] = v.x; q2[i + 1] = v.y;
    }

    ull o2[32];
    #pragma unroll
    for (int i = 0; i < 32; i++) o2[i] = 0ull;   // bits of (+0.f, +0.f)
    float mmax = -1e30f, l = 0.f;

    const float* kb   = g_k + (size_t)bh * T_LEN * HDIM;
    const float* vb   = g_v + (size_t)bh * T_LEN * HDIM;
    const float* mrow = mask + (size_t)t * T_LEN;

    for (int s0 = 0; s0 < T_LEN; s0 += 64) {
        __syncthreads();
        #pragma unroll
        for (int i = threadIdx.x; i < 64 * 64 / 4; i += 128) {
            ((float4*)Ks)[i] = ((const float4*)(kb + (size_t)s0 * HDIM))[i];
            ((float4*)Vs)[i] = ((const float4*)(vb + (size_t)s0 * HDIM))[i];
        }
        __syncthreads();

        #pragma unroll 1
        for (int g = 0; g < 64; g += 16) {
            float s[16];
            #pragma unroll
            for (int j = 0; j < 16; j++) {
                const float* kr = Ks + (g + j) * 64;
                ull a0 = 0ull, a1 = 0ull, a2v = 0ull, a3 = 0ull;
                #pragma unroll
                for (int d = 0; d < 32; d += 8) {        // d in pair units
                    ulonglong2 kA = *(const ulonglong2*)(kr + 2 * d);
                    ulonglong2 kB = *(const ulonglong2*)(kr + 2 * d + 4);
                    ulonglong2 kC = *(const ulonglong2*)(kr + 2 * d + 8);
                    ulonglong2 kD = *(const ulonglong2*)(kr + 2 * d + 12);
                    a0  = fma2(q2[d + 0], kA.x, a0);
                    a1  = fma2(q2[d + 1], kA.y, a1);
                    a2v = fma2(q2[d + 2], kB.x, a2v);
                    a3  = fma2(q2[d + 3], kB.y, a3);
                    a0  = fma2(q2[d + 4], kC.x, a0);
                    a1  = fma2(q2[d + 5], kC.y, a1);
                    a2v = fma2(q2[d + 6], kD.x, a2v);
                    a3  = fma2(q2[d + 7], kD.y, a3);
                }
                ull tsum = add2(add2(a0, a1), add2(a2v, a3));
                float lo, hi;
                unpack2(tsum, lo, hi);
                s[j] = lo + hi;
            }
            // additive mask (16 keys)
            #pragma unroll
            for (int j = 0; j < 16; j += 4) {
                float4 mv = *(const float4*)(mrow + s0 + g + j);
                s[j + 0] += mv.x; s[j + 1] += mv.y;
                s[j + 2] += mv.z; s[j + 3] += mv.w;
            }

            // online softmax update
            float tmax = mmax;
            #pragma unroll
            for (int j = 0; j < 16; j++) tmax = fmaxf(tmax, s[j]);
            float corr = __expf(mmax - tmax);
            mmax = tmax;
            l *= corr;
            ull cc = pack2(corr, corr);
            #pragma unroll
            for (int i = 0; i < 32; i++) o2[i] = mul2(o2[i], cc);

            float p[16];
            #pragma unroll
            for (int j = 0; j < 16; j++) { p[j] = __expf(s[j] - tmax); l += p[j]; }

            #pragma unroll
            for (int j = 0; j < 16; j++) {
                const float* vr = Vs + (g + j) * 64;
                ull pj = pack2(p[j], p[j]);
                #pragma unroll
                for (int d = 0; d < 32; d += 4) {
                    ulonglong2 vA = *(const ulonglong2*)(vr + 2 * d);
                    ulonglong2 vB = *(const ulonglong2*)(vr + 2 * d + 4);
                    o2[d + 0] = fma2(pj, vA.x, o2[d + 0]);
                    o2[d + 1] = fma2(pj, vA.y, o2[d + 1]);
                    o2[d + 2] = fma2(pj, vB.x, o2[d + 2]);
                    o2[d + 3] = fma2(pj, vB.y, o2[d + 3]);
                }
            }
        }
    }

    const float inv = 1.0f / l;
    const ull inv2 = pack2(inv, inv);
    const int b = bh / NH, h = bh % NH;
    float* dst = attn_out + ((size_t)t * BSZ + b) * EMB + h * HDIM;
    #pragma unroll
    for (int i = 0; i < 32; i += 2) {
        ulonglong2 r;
        r.x = mul2(o2[i], inv2);
        r.y = mul2(o2[i + 1], inv2);
        *(ulonglong2*)(dst + 2 * i) = r;
    }
}

// ============================================================================
// Launch
// ============================================================================
extern "C" void kernel_launch(void* const* d_in, const int* in_sizes, int n_in,
                              void* d_out, int out_size)
{
    const float* query  = (const float*)d_in[0];
    const float* key    = (const float*)d_in[1];
    const float* value  = (const float*)d_in[2];
    const float* mask   = (const float*)d_in[3];
    const float* in_w   = (const float*)d_in[4];
    const float* in_b   = (const float*)d_in[5];
    const float* out_w  = (const float*)d_in[6];
    const float* out_b  = (const float*)d_in[7];
    float* out = (float*)d_out;

    float* attn_ptr;
    cudaGetSymbolAddress((void**)&attn_ptr, g_attn);

    // 1) QKV projection (z = 0/1/2 -> q/k/v), scatter to per-head layout
    qkv_gemm<<<dim3(EMB / BN, MROWS / BM, 3), 256>>>(query, key, value, in_w, in_b);

    // 2) Attention (32 (b,h) heads x 16 query tiles)
    flash_attn<<<dim3(T_LEN / 128, BSZ * NH), 128>>>(mask, attn_ptr);

    // 3) Output projection directly into d_out
    out_gemm<<<dim3(DMODEL / BN, MROWS / BM), 256>>>(out_w, out_b, out);
}

// round 4
// speedup vs baseline: 2.6235x; 2.6235x over previous
#include <cuda_runtime.h>
#include <cuda_bf16.h>
#include <cstdint>

#define T_LEN 2048
#define BSZ   2
#define DM    1024
#define NH    16
#define HD    64
#define EMB   1024
#define MROWS 4096

// ---------------- scratch (allocation-free: device globals) ----------------
// q/k/v pre-split into bf16 hi/lo by the QKV epilogue; layout [b*NH+h][t][d]
__device__ __nv_bfloat16 g_qh[(size_t)BSZ * NH * T_LEN * HD];
__device__ __nv_bfloat16 g_ql[(size_t)BSZ * NH * T_LEN * HD];
__device__ __nv_bfloat16 g_kh[(size_t)BSZ * NH * T_LEN * HD];
__device__ __nv_bfloat16 g_kl[(size_t)BSZ * NH * T_LEN * HD];
__device__ __nv_bfloat16 g_vh[(size_t)BSZ * NH * T_LEN * HD];
__device__ __nv_bfloat16 g_vl[(size_t)BSZ * NH * T_LEN * HD];
__device__ float g_attn[(size_t)MROWS * EMB];   // [t*B+b][e]

// ============================ PTX helpers ===================================
__device__ __forceinline__ uint32_t su32(const void* p) {
    uint32_t a;
    asm("{ .reg .u64 t; cvta.to.shared.u64 t, %1; cvt.u32.u64 %0, t; }"
        : "=r"(a) : "l"(p));
    return a;
}
__device__ __forceinline__ void ldsm4(uint32_t r[4], uint32_t a) {
    asm volatile("ldmatrix.sync.aligned.m8n8.x4.shared.b16 {%0,%1,%2,%3}, [%4];"
                 : "=r"(r[0]), "=r"(r[1]), "=r"(r[2]), "=r"(r[3]) : "r"(a));
}
__device__ __forceinline__ void ldsm4t(uint32_t r[4], uint32_t a) {
    asm volatile("ldmatrix.sync.aligned.m8n8.x4.trans.shared.b16 {%0,%1,%2,%3}, [%4];"
                 : "=r"(r[0]), "=r"(r[1]), "=r"(r[2]), "=r"(r[3]) : "r"(a));
}
__device__ __forceinline__ void mma_bf(float c[4], const uint32_t a[4],
                                       const uint32_t b[2]) {
    asm volatile(
        "mma.sync.aligned.m16n8k16.row.col.f32.bf16.bf16.f32 "
        "{%0,%1,%2,%3}, {%4,%5,%6,%7}, {%8,%9}, {%0,%1,%2,%3};"
        : "+f"(c[0]), "+f"(c[1]), "+f"(c[2]), "+f"(c[3])
        : "r"(a[0]), "r"(a[1]), "r"(a[2]), "r"(a[3]), "r"(b[0]), "r"(b[1]));
}

// ---------------- bf16 hi/lo split helpers ---------------------------------
__device__ __forceinline__ void spl1(float x, uint16_t& h, float& r) {
    __nv_bfloat16 hb = __float2bfloat16_rn(x);
    r = x - __bfloat162float(hb);
    h = *reinterpret_cast<uint16_t*>(&hb);
}
__device__ __forceinline__ uint32_t pkf(float a, float b) {
    __nv_bfloat162 t = __halves2bfloat162(__float2bfloat16_rn(a),
                                          __float2bfloat16_rn(b));
    return *reinterpret_cast<uint32_t*>(&t);
}
__device__ __forceinline__ void spl_pair(float x0, float x1,
                                         uint32_t& H, uint32_t& L) {
    uint16_t h0, h1; float r0, r1;
    spl1(x0, h0, r0); spl1(x1, h1, r1);
    H = (uint32_t)h0 | ((uint32_t)h1 << 16);
    L = pkf(r0, r1);
}
__device__ __forceinline__ void cvt8(const float4& a, const float4& b,
                                     uint4& H, uint4& L) {
    uint16_t h[8]; float r[8];
    spl1(a.x, h[0], r[0]); spl1(a.y, h[1], r[1]);
    spl1(a.z, h[2], r[2]); spl1(a.w, h[3], r[3]);
    spl1(b.x, h[4], r[4]); spl1(b.y, h[5], r[5]);
    spl1(b.z, h[6], r[6]); spl1(b.w, h[7], r[7]);
    H.x = (uint32_t)h[0] | ((uint32_t)h[1] << 16);
    H.y = (uint32_t)h[2] | ((uint32_t)h[3] << 16);
    H.z = (uint32_t)h[4] | ((uint32_t)h[5] << 16);
    H.w = (uint32_t)h[6] | ((uint32_t)h[7] << 16);
    L.x = pkf(r[0], r[1]); L.y = pkf(r[2], r[3]);
    L.z = pkf(r[4], r[5]); L.w = pkf(r[6], r[7]);
}

// ============================================================================
// GEMM core (TN, bf16x3 mma.sync): CTA tile 128x64, K=1024, chunk 32.
// smem per stage: Ah(128x32) Al Wh(64x32) Wl, row stride 80B (conflict-free).
// 8 warps as 4(m) x 2(n): warp tile 32x32 = 2 m16 x 4 n8 frags.
// ============================================================================
#define GRS 80
#define G_AH 0
#define G_AL 10240
#define G_WH 20480
#define G_WL 25600
#define G_STAGE 30720
#define G_SMEM (2 * G_STAGE)

__device__ __forceinline__ void gemm_core(
    const float* __restrict__ A, const float* __restrict__ W,
    int m0, int n0, char* sm, float (&acc)[2][4][4])
{
    const int tid = threadIdx.x;
    const int lane = tid & 31;
    const int wid = tid >> 5;
    const int mq = wid & 3;          // 0..3 : 32-row quad
    const int nh2 = wid >> 2;        // 0..1 : 32-col half
    const uint32_t sb = su32(sm);

    #pragma unroll
    for (int i = 0; i < 2; i++)
        #pragma unroll
        for (int j = 0; j < 4; j++)
            #pragma unroll
            for (int v = 0; v < 4; v++) acc[i][j][v] = 0.f;

    const float* arow = A + (size_t)(m0 + (tid >> 1)) * DM + (tid & 1) * 16;
    const float* wrow = W + (size_t)(n0 + (tid >> 2)) * DM + (tid & 3) * 8;
    const int aoff = (tid >> 1) * GRS + (tid & 1) * 32;
    const int woff = (tid >> 2) * GRS + (tid & 3) * 16;

    float4 ra0, ra1, ra2, ra3, rw0, rw1;

    // prologue: load + stage chunk 0
    ra0 = *(const float4*)(arow + 0);  ra1 = *(const float4*)(arow + 4);
    ra2 = *(const float4*)(arow + 8);  ra3 = *(const float4*)(arow + 12);
    rw0 = *(const float4*)(wrow + 0);  rw1 = *(const float4*)(wrow + 4);
    {
        uint4 H, L;
        cvt8(ra0, ra1, H, L);
        *(uint4*)(sm + G_AH + aoff) = H;      *(uint4*)(sm + G_AL + aoff) = L;
        cvt8(ra2, ra3, H, L);
        *(uint4*)(sm + G_AH + aoff + 16) = H; *(uint4*)(sm + G_AL + aoff + 16) = L;
        cvt8(rw0, rw1, H, L);
        *(uint4*)(sm + G_WH + woff) = H;      *(uint4*)(sm + G_WL + woff) = L;
    }
    __syncthreads();

    const int a_l = (mq * 32 + (lane & 15)) * GRS + ((lane >> 4) << 3) * 2;
    const int b_l = (nh2 * 32 + ((lane >> 4) << 3) + (lane & 7)) * GRS + (lane & 8) * 2;

    for (int c = 0; c < 32; c++) {
        if (c < 31) {
            const float* ap = arow + (c + 1) * 32;
            const float* wp = wrow + (c + 1) * 32;
            ra0 = *(const float4*)(ap + 0);  ra1 = *(const float4*)(ap + 4);
            ra2 = *(const float4*)(ap + 8);  ra3 = *(const float4*)(ap + 12);
            rw0 = *(const float4*)(wp + 0);  rw1 = *(const float4*)(wp + 4);
        }

        const uint32_t st = sb + (c & 1) * G_STAGE;
        #pragma unroll
        for (int kk = 0; kk < 2; kk++) {
            uint32_t ah[2][4], al[2][4], bh[4][2], bl[4][2];
            #pragma unroll
            for (int mi = 0; mi < 2; mi++) {
                uint32_t ad = st + G_AH + a_l + mi * 16 * GRS + kk * 32;
                ldsm4(ah[mi], ad);
                ldsm4(al[mi], ad + (G_AL - G_AH));
            }
            #pragma unroll
            for (int np = 0; np < 2; np++) {
                uint32_t bd = st + G_WH + b_l + np * 16 * GRS + kk * 32;
                uint32_t t[4];
                ldsm4(t, bd);
                bh[np * 2][0] = t[0]; bh[np * 2][1] = t[1];
                bh[np * 2 + 1][0] = t[2]; bh[np * 2 + 1][1] = t[3];
                ldsm4(t, bd + (G_WL - G_WH));
                bl[np * 2][0] = t[0]; bl[np * 2][1] = t[1];
                bl[np * 2 + 1][0] = t[2]; bl[np * 2 + 1][1] = t[3];
            }
            #pragma unroll
            for (int mi = 0; mi < 2; mi++)
                #pragma unroll
                for (int ni = 0; ni < 4; ni++) {
                    mma_bf(acc[mi][ni], ah[mi], bh[ni]);
                    mma_bf(acc[mi][ni], ah[mi], bl[ni]);
                    mma_bf(acc[mi][ni], al[mi], bh[ni]);
                }
        }
        __syncthreads();
        if (c < 31) {
            char* so = sm + ((c + 1) & 1) * G_STAGE;
            uint4 H, L;
            cvt8(ra0, ra1, H, L);
            *(uint4*)(so + G_AH + aoff) = H;      *(uint4*)(so + G_AL + aoff) = L;
            cvt8(ra2, ra3, H, L);
            *(uint4*)(so + G_AH + aoff + 16) = H; *(uint4*)(so + G_AL + aoff + 16) = L;
            cvt8(rw0, rw1, H, L);
            *(uint4*)(so + G_WH + woff) = H;      *(uint4*)(so + G_WL + woff) = L;
            __syncthreads();
        }
    }
}

// -------- QKV projection: z selects q/k/v; writes bf16 hi/lo per-head ------
__global__ __launch_bounds__(256) void qkv_gemm(
    const float* __restrict__ Xq, const float* __restrict__ Xk,
    const float* __restrict__ Xv, const float* __restrict__ W,
    const float* __restrict__ bias)
{
    extern __shared__ char sm[];
    const int z = blockIdx.z;
    const float* A  = (z == 0) ? Xq : (z == 1) ? Xk : Xv;
    const float* Wz = W + (size_t)z * EMB * DM;
    const float* bz = bias + (size_t)z * EMB;
    __nv_bfloat16* dh = (z == 0) ? g_qh : (z == 1) ? g_kh : g_vh;
    __nv_bfloat16* dl = (z == 0) ? g_ql : (z == 1) ? g_kl : g_vl;

    const int m0 = blockIdx.y * 128;
    const int n0 = blockIdx.x * 64;

    float acc[2][4][4];
    gemm_core(A, Wz, m0, n0, sm, acc);

    const int lane = threadIdx.x & 31, wid = threadIdx.x >> 5;
    const int mq = wid & 3, nh2 = wid >> 2;
    const int g = lane >> 2, t4 = lane & 3;
    const float scale = (z == 0) ? 0.125f : 1.0f;

    #pragma unroll
    for (int mi = 0; mi < 2; mi++) {
        #pragma unroll
        for (int ni = 0; ni < 4; ni++) {
            const int mrow = m0 + mq * 32 + mi * 16 + g;
            const int ncol = n0 + nh2 * 32 + ni * 8 + t4 * 2;
            const float b0 = __ldg(&bz[ncol]), b1 = __ldg(&bz[ncol + 1]);
            const int h = ncol >> 6, d = ncol & 63;
            #pragma unroll
            for (int rr = 0; rr < 2; rr++) {
                const int m = mrow + rr * 8;
                const int t = m >> 1, b = m & 1;
                const float v0 = (acc[mi][ni][rr * 2 + 0] + b0) * scale;
                const float v1 = (acc[mi][ni][rr * 2 + 1] + b1) * scale;
                uint32_t H, L;
                spl_pair(v0, v1, H, L);
                const size_t idx = ((size_t)(b * NH + h) * T_LEN + t) * HD + d;
                *(uint32_t*)(dh + idx) = H;
                *(uint32_t*)(dl + idx) = L;
            }
        }
    }
}

// -------- Output projection: C = g_attn @ Wo^T + bo ------------------------
__global__ __launch_bounds__(256) void out_gemm(
    const float* __restrict__ W, const float* __restrict__ bias,
    float* __restrict__ C)
{
    extern __shared__ char sm[];
    const int m0 = blockIdx.y * 128;
    const int n0 = blockIdx.x * 64;

    float acc[2][4][4];
    gemm_core(g_attn, W, m0, n0, sm, acc);

    const int lane = threadIdx.x & 31, wid = threadIdx.x >> 5;
    const int mq = wid & 3, nh2 = wid >> 2;
    const int g = lane >> 2, t4 = lane & 3;

    #pragma unroll
    for (int mi = 0; mi < 2; mi++) {
        #pragma unroll
        for (int ni = 0; ni < 4; ni++) {
            const int mrow = m0 + mq * 32 + mi * 16 + g;
            const int ncol = n0 + nh2 * 32 + ni * 8 + t4 * 2;
            const float b0 = __ldg(&bias[ncol]), b1 = __ldg(&bias[ncol + 1]);
            #pragma unroll
            for (int rr = 0; rr < 2; rr++) {
                const int m = mrow + rr * 8;
                float2 v;
                v.x = acc[mi][ni][rr * 2 + 0] + b0;
                v.y = acc[mi][ni][rr * 2 + 1] + b1;
                *(float2*)(C + (size_t)m * DM + ncol) = v;
            }
        }
    }
}

// ============================================================================
// Flash attention with mma.sync bf16x3. CTA = 64 q-rows x one (b,h); 4 warps,
// each warp 16 q-rows. K/V tiles 64x64 bf16 hi/lo staged in smem (144B rows).
// ============================================================================
#define ARS 144
#define A_QH 0
#define A_QL 9216
#define A_KH 18432
#define A_KL 27648
#define A_VH 36864
#define A_VL 46080
#define A_SMEM 55296

__global__ __launch_bounds__(128) void flash_mma(const float* __restrict__ mask,
                                                 float* __restrict__ attn_out)
{
    extern __shared__ char sm[];
    const int tid = threadIdx.x, lane = tid & 31, w = tid >> 5;
    const int bh = blockIdx.y, qt = blockIdx.x;
    const int g = lane >> 2, t4 = lane & 3;
    const uint32_t sb = su32(sm);

    const size_t hbase = (size_t)bh * T_LEN;

    // ---- stage Q tile (bf16 hi/lo straight copy) ----
    {
        const int r = tid >> 1, co = (tid & 1) * 64;      // row, byte col
        const __nv_bfloat16* sqh = g_qh + (hbase + qt * 64 + r) * HD + co / 2;
        const __nv_bfloat16* sql = g_ql + (hbase + qt * 64 + r) * HD + co / 2;
        #pragma unroll
        for (int i = 0; i < 4; i++) {
            *(uint4*)(sm + A_QH + r * ARS + co + i * 16) = *(const uint4*)(sqh + i * 8);
            *(uint4*)(sm + A_QL + r * ARS + co + i * 16) = *(const uint4*)(sql + i * 8);
        }
    }
    __syncthreads();

    uint32_t qh[4][4], ql[4][4];
    #pragma unroll
    for (int j = 0; j < 4; j++) {
        uint32_t a = sb + A_QH + (w * 16 + (lane & 15)) * ARS +
                     (j * 16 + ((lane >> 4) << 3)) * 2;
        ldsm4(qh[j], a);
        ldsm4(ql[j], a + (A_QL - A_QH));
    }

    float oacc[8][4];
    #pragma unroll
    for (int i = 0; i < 8; i++)
        #pragma unroll
        for (int v = 0; v < 4; v++) oacc[i][v] = 0.f;
    float m0r = -1e30f, m1r = -1e30f, l0 = 0.f, l1 = 0.f;

    const int tq = qt * 64 + w * 16 + g;
    const float* mrow0 = mask + (size_t)tq * T_LEN;
    const float* mrow1 = mask + (size_t)(tq + 8) * T_LEN;

    for (int it = 0; it < 32; it++) {
        const int s0 = it * 64;
        __syncthreads();
        {   // ---- stage K/V tiles ----
            const int r = tid >> 1, co = (tid & 1) * 64;
            const size_t src = (hbase + s0 + r) * HD + co / 2;
            #pragma unroll
            for (int i = 0; i < 4; i++) {
                *(uint4*)(sm + A_KH + r * ARS + co + i * 16) = *(const uint4*)(g_kh + src + i * 8);
                *(uint4*)(sm + A_KL + r * ARS + co + i * 16) = *(const uint4*)(g_kl + src + i * 8);
                *(uint4*)(sm + A_VH + r * ARS + co + i * 16) = *(const uint4*)(g_vh + src + i * 8);
                *(uint4*)(sm + A_VL + r * ARS + co + i * 16) = *(const uint4*)(g_vl + src + i * 8);
            }
        }
        __syncthreads();

        // ---- S = Q K^T (bf16x3) ----
        float sacc[8][4];
        #pragma unroll
        for (int i = 0; i < 8; i++)
            #pragma unroll
            for (int v = 0; v < 4; v++) sacc[i][v] = 0.f;

        #pragma unroll
        for (int j = 0; j < 4; j++) {
            uint32_t kbh[8][2], kbl[8][2];
            #pragma unroll
            for (int np = 0; np < 4; np++) {
                uint32_t bd = sb + A_KH +
                              (np * 16 + ((lane >> 4) << 3) + (lane & 7)) * ARS +
                              (j * 16 + (lane & 8)) * 2;
                uint32_t t[4];
                ldsm4(t, bd);
                kbh[np * 2][0] = t[0]; kbh[np * 2][1] = t[1];
                kbh[np * 2 + 1][0] = t[2]; kbh[np * 2 + 1][1] = t[3];
                ldsm4(t, bd + (A_KL - A_KH));
                kbl[np * 2][0] = t[0]; kbl[np * 2][1] = t[1];
                kbl[np * 2 + 1][0] = t[2]; kbl[np * 2 + 1][1] = t[3];
            }
            #pragma unroll
            for (int jn = 0; jn < 8; jn++) {
                mma_bf(sacc[jn], qh[j], kbh[jn]);
                mma_bf(sacc[jn], qh[j], kbl[jn]);
                mma_bf(sacc[jn], ql[j], kbh[jn]);
            }
        }

        // ---- mask + online softmax ----
        float mx0 = -1e30f, mx1 = -1e30f;
        #pragma unroll
        for (int jn = 0; jn < 8; jn++) {
            const int sc = s0 + jn * 8 + t4 * 2;
            float2 ma = *(const float2*)(mrow0 + sc);
            float2 mb = *(const float2*)(mrow1 + sc);
            sacc[jn][0] += ma.x; sacc[jn][1] += ma.y;
            sacc[jn][2] += mb.x; sacc[jn][3] += mb.y;
            mx0 = fmaxf(mx0, fmaxf(sacc[jn][0], sacc[jn][1]));
            mx1 = fmaxf(mx1, fmaxf(sacc[jn][2], sacc[jn][3]));
        }
        mx0 = fmaxf(mx0, __shfl_xor_sync(0xffffffffu, mx0, 1));
        mx0 = fmaxf(mx0, __shfl_xor_sync(0xffffffffu, mx0, 2));
        mx1 = fmaxf(mx1, __shfl_xor_sync(0xffffffffu, mx1, 1));
        mx1 = fmaxf(mx1, __shfl_xor_sync(0xffffffffu, mx1, 2));

        const float mn0 = fmaxf(m0r, mx0), mn1 = fmaxf(m1r, mx1);
        const float c0 = __expf(m0r - mn0), c1 = __expf(m1r - mn1);
        m0r = mn0; m1r = mn1;
        l0 *= c0; l1 *= c1;
        #pragma unroll
        for (int jd = 0; jd < 8; jd++) {
            oacc[jd][0] *= c0; oacc[jd][1] *= c0;
            oacc[jd][2] *= c1; oacc[jd][3] *= c1;
        }
        #pragma unroll
        for (int jn = 0; jn < 8; jn++) {
            sacc[jn][0] = __expf(sacc[jn][0] - mn0);
            sacc[jn][1] = __expf(sacc[jn][1] - mn0);
            sacc[jn][2] = __expf(sacc[jn][2] - mn1);
            sacc[jn][3] = __expf(sacc[jn][3] - mn1);
            l0 += sacc[jn][0] + sacc[jn][1];
            l1 += sacc[jn][2] + sacc[jn][3];
        }

        // ---- O += P V (bf16x3) ----
        #pragma unroll
        for (int js = 0; js < 4; js++) {
            uint32_t ph[4], pl[4];
            spl_pair(sacc[2 * js][0], sacc[2 * js][1], ph[0], pl[0]);
            spl_pair(sacc[2 * js][2], sacc[2 * js][3], ph[1], pl[1]);
            spl_pair(sacc[2 * js + 1][0], sacc[2 * js + 1][1], ph[2], pl[2]);
            spl_pair(sacc[2 * js + 1][2], sacc[2 * js + 1][3], ph[3], pl[3]);

            uint32_t vbh[8][2], vbl[8][2];
            #pragma unroll
            for (int dp = 0; dp < 4; dp++) {
                uint32_t vd = sb + A_VH + (js * 16 + (lane & 15)) * ARS +
                              (dp * 16 + ((lane >> 4) << 3)) * 2;
                uint32_t t[4];
                ldsm4t(t, vd);
                vbh[dp * 2][0] = t[0]; vbh[dp * 2][1] = t[1];
                vbh[dp * 2 + 1][0] = t[2]; vbh[dp * 2 + 1][1] = t[3];
                ldsm4t(t, vd + (A_VL - A_VH));
                vbl[dp * 2][0] = t[0]; vbl[dp * 2][1] = t[1];
                vbl[dp * 2 + 1][0] = t[2]; vbl[dp * 2 + 1][1] = t[3];
            }
            #pragma unroll
            for (int jd = 0; jd < 8; jd++) {
                mma_bf(oacc[jd], ph, vbh[jd]);
                mma_bf(oacc[jd], ph, vbl[jd]);
                mma_bf(oacc[jd], pl, vbh[jd]);
            }
        }
    }

    l0 += __shfl_xor_sync(0xffffffffu, l0, 1);
    l0 += __shfl_xor_sync(0xffffffffu, l0, 2);
    l1 += __shfl_xor_sync(0xffffffffu, l1, 1);
    l1 += __shfl_xor_sync(0xffffffffu, l1, 2);
    const float i0 = 1.0f / l0, i1 = 1.0f / l1;

    const int b = bh >> 4, h = bh & 15;
    #pragma unroll
    for (int jd = 0; jd < 8; jd++) {
        const int d = jd * 8 + t4 * 2;
        float2 va, vb;
        va.x = oacc[jd][0] * i0; va.y = oacc[jd][1] * i0;
        vb.x = oacc[jd][2] * i1; vb.y = oacc[jd][3] * i1;
        *(float2*)(g_attn + ((size_t)tq * BSZ + b) * EMB + h * HD + d) = va;
        *(float2*)(g_attn + ((size_t)(tq + 8) * BSZ + b) * EMB + h * HD + d) = vb;
    }
    (void)attn_out;
}

// ============================================================================
// Launch
// ============================================================================
extern "C" void kernel_launch(void* const* d_in, const int* in_sizes, int n_in,
                              void* d_out, int out_size)
{
    const float* query  = (const float*)d_in[0];
    const float* key    = (const float*)d_in[1];
    const float* value  = (const float*)d_in[2];
    const float* mask   = (const float*)d_in[3];
    const float* in_w   = (const float*)d_in[4];
    const float* in_b   = (const float*)d_in[5];
    const float* out_w  = (const float*)d_in[6];
    const float* out_b  = (const float*)d_in[7];
    float* out = (float*)d_out;

    static bool attr_done = false;
    if (!attr_done) {
        cudaFuncSetAttribute(qkv_gemm, cudaFuncAttributeMaxDynamicSharedMemorySize, G_SMEM);
        cudaFuncSetAttribute(out_gemm, cudaFuncAttributeMaxDynamicSharedMemorySize, G_SMEM);
        cudaFuncSetAttribute(flash_mma, cudaFuncAttributeMaxDynamicSharedMemorySize, A_SMEM);
        attr_done = true;
    }

    // 1) QKV projection -> pre-split bf16 hi/lo per-head layout
    qkv_gemm<<<dim3(EMB / 64, MROWS / 128, 3), 256, G_SMEM>>>(
        query, key, value, in_w, in_b);

    // 2) Attention (mma.sync bf16x3 flash) -> g_attn (f32)
    flash_mma<<<dim3(T_LEN / 64, BSZ * NH), 128, A_SMEM>>>(mask, nullptr);

    // 3) Output projection (mma.sync bf16x3) -> d_out
    out_gemm<<<dim3(DM / 64, MROWS / 128), 256, G_SMEM>>>(out_w, out_b, out);
}

// round 5
// speedup vs baseline: 4.4978x; 1.7145x over previous
#include <cuda_runtime.h>
#include <cuda_fp16.h>
#include <cstdint>

#define T_LEN 2048
#define BSZ   2
#define DM    1024
#define NH    16
#define HD    64
#define EMB   1024
#define MROWS 4096
#define NELEM ((size_t)MROWS * DM)          // 4M elements per input tensor

// ---------------- scratch (allocation-free: device globals) ----------------
__device__ __half g_inh[3 * NELEM];         // inputs split hi (q,k,v)
__device__ __half g_inl[3 * NELEM];         // inputs split lo
__device__ __half g_wih[(size_t)3 * EMB * DM];  // in_proj_weight fp16
__device__ __half g_woh[(size_t)DM * EMB];      // out_proj_weight fp16
__device__ __half g_qh[(size_t)BSZ * NH * T_LEN * HD];  // q hi (unscaled)
__device__ __half g_ql[(size_t)BSZ * NH * T_LEN * HD];  // q lo
__device__ __half g_kh[(size_t)BSZ * NH * T_LEN * HD];  // k fp16
__device__ __half g_vh[(size_t)BSZ * NH * T_LEN * HD];  // v fp16
__device__ __half g_ah[NELEM];              // attn out hi  [t*B+b][e]
__device__ __half g_al[NELEM];              // attn out lo

// ============================ PTX helpers ===================================
__device__ __forceinline__ uint32_t su32(const void* p) {
    uint32_t a;
    asm("{ .reg .u64 t; cvta.to.shared.u64 t, %1; cvt.u32.u64 %0, t; }"
        : "=r"(a) : "l"(p));
    return a;
}
__device__ __forceinline__ void cpa(uint32_t s, const void* g) {
    asm volatile("cp.async.cg.shared.global [%0], [%1], 16;" :: "r"(s), "l"(g));
}
__device__ __forceinline__ void cp_commit() {
    asm volatile("cp.async.commit_group;" ::: "memory");
}
__device__ __forceinline__ void cp_wait0() {
    asm volatile("cp.async.wait_group 0;" ::: "memory");
}
__device__ __forceinline__ void cp_wait1() {
    asm volatile("cp.async.wait_group 1;" ::: "memory");
}
__device__ __forceinline__ void cp_wait2() {
    asm volatile("cp.async.wait_group 2;" ::: "memory");
}
__device__ __forceinline__ void ldsm4(uint32_t r[4], uint32_t a) {
    asm volatile("ldmatrix.sync.aligned.m8n8.x4.shared.b16 {%0,%1,%2,%3}, [%4];"
                 : "=r"(r[0]), "=r"(r[1]), "=r"(r[2]), "=r"(r[3]) : "r"(a));
}
__device__ __forceinline__ void ldsm4t(uint32_t r[4], uint32_t a) {
    asm volatile("ldmatrix.sync.aligned.m8n8.x4.trans.shared.b16 {%0,%1,%2,%3}, [%4];"
                 : "=r"(r[0]), "=r"(r[1]), "=r"(r[2]), "=r"(r[3]) : "r"(a));
}
__device__ __forceinline__ void mma_f16(float c[4], const uint32_t a[4],
                                        const uint32_t b[2]) {
    asm volatile(
        "mma.sync.aligned.m16n8k16.row.col.f32.f16.f16.f32 "
        "{%0,%1,%2,%3}, {%4,%5,%6,%7}, {%8,%9}, {%0,%1,%2,%3};"
        : "+f"(c[0]), "+f"(c[1]), "+f"(c[2]), "+f"(c[3])
        : "r"(a[0]), "r"(a[1]), "r"(a[2]), "r"(a[3]), "r"(b[0]), "r"(b[1]));
}

// ---------------- fp16 split helpers ----------------------------------------
__device__ __forceinline__ void fspl1(float x, uint16_t& h, float& r) {
    __half hb = __float2half_rn(x);
    r = x - __half2float(hb);
    h = __half_as_ushort(hb);
}
__device__ __forceinline__ uint32_t fpk(float a, float b) {
    __half2 t = __floats2half2_rn(a, b);
    return *reinterpret_cast<uint32_t*>(&t);
}
__device__ __forceinline__ void fspl_pair(float x0, float x1,
                                          uint32_t& H, uint32_t& L) {
    uint16_t h0, h1; float r0, r1;
    fspl1(x0, h0, r0); fspl1(x1, h1, r1);
    H = (uint32_t)h0 | ((uint32_t)h1 << 16);
    L = fpk(r0, r1);
}

// ============================================================================
// Prep kernels: split inputs into fp16 hi/lo; convert weights to fp16.
// ============================================================================
__global__ __launch_bounds__(256) void prep_split(
    const float* __restrict__ q, const float* __restrict__ k,
    const float* __restrict__ v)
{
    const int z = blockIdx.y;
    const float* s = (z == 0) ? q : (z == 1) ? k : v;
    __half* dh = g_inh + (size_t)z * NELEM;
    __half* dl = g_inl + (size_t)z * NELEM;
    const size_t i = ((size_t)blockIdx.x * 256 + threadIdx.x) * 4;
    float4 x = *(const float4*)(s + i);
    uint16_t h0, h1, h2, h3; float r0, r1, r2, r3;
    fspl1(x.x, h0, r0); fspl1(x.y, h1, r1);
    fspl1(x.z, h2, r2); fspl1(x.w, h3, r3);
    uint2 H, L;
    H.x = (uint32_t)h0 | ((uint32_t)h1 << 16);
    H.y = (uint32_t)h2 | ((uint32_t)h3 << 16);
    L.x = fpk(r0, r1); L.y = fpk(r2, r3);
    *(uint2*)(dh + i) = H;
    *(uint2*)(dl + i) = L;
}

__global__ __launch_bounds__(256) void prep_cvt(const float* __restrict__ s,
                                                int which, int n)
{
    __half* d = which ? g_woh : g_wih;
    const int i = (blockIdx.x * 256 + threadIdx.x) * 4;
    if (i < n) {
        float4 x = *(const float4*)(s + i);
        uint2 H;
        H.x = fpk(x.x, x.y);
        H.y = fpk(x.z, x.w);
        *(uint2*)(d + i) = H;
    }
}

// ============================================================================
// GEMM core (TN, fp16 x2): CTA 128x64, chunk K=32, cp.async double-buffered.
// smem/stage: Ah[128x32] Al Wh[64x32] fp16, row stride 80B. 8 warps = 4m x 2n.
// ============================================================================
#define GRS 80
#define S_AH 0
#define S_AL 10240
#define S_WH 20480
#define G_STAGE 25600
#define G_SMEM (2 * G_STAGE)

__device__ __forceinline__ void g_load(uint32_t sb, const __half* Ah,
                                       const __half* Al, const __half* Wg,
                                       int m0, int n0, int c, int tid)
{
    const uint32_t st = sb + (c & 1) * G_STAGE;
    const int k0 = c * 32;
    #pragma unroll
    for (int i = 0; i < 2; i++) {
        const int idx = tid + i * 256;
        const int row = idx >> 2, cc = idx & 3;
        const uint32_t o = row * GRS + cc * 16;
        const size_t src = (size_t)(m0 + row) * DM + k0 + cc * 8;
        cpa(st + S_AH + o, Ah + src);
        cpa(st + S_AL + o, Al + src);
    }
    {
        const int row = tid >> 2, cc = tid & 3;
        cpa(st + S_WH + row * GRS + cc * 16,
            Wg + (size_t)(n0 + row) * DM + k0 + cc * 8);
    }
    cp_commit();
}

__device__ __forceinline__ void gemm_core(
    const __half* __restrict__ Ah, const __half* __restrict__ Al,
    const __half* __restrict__ Wg, int m0, int n0, uint32_t sb,
    float (&acc)[2][4][4])
{
    const int tid = threadIdx.x, lane = tid & 31, wid = tid >> 5;
    const int mq = wid & 3, nh2 = wid >> 2;

    #pragma unroll
    for (int i = 0; i < 2; i++)
        #pragma unroll
        for (int j = 0; j < 4; j++)
            #pragma unroll
            for (int v = 0; v < 4; v++) acc[i][j][v] = 0.f;

    g_load(sb, Ah, Al, Wg, m0, n0, 0, tid);
    g_load(sb, Ah, Al, Wg, m0, n0, 1, tid);

    const int a_l = (mq * 32 + (lane & 15)) * GRS + ((lane >> 4) << 3) * 2;
    const int b_l = (nh2 * 32 + ((lane >> 4) << 3) + (lane & 7)) * GRS + (lane & 8) * 2;

    for (int c = 0; c < 32; c++) {
        if (c == 31) cp_wait0(); else cp_wait1();
        __syncthreads();
        const uint32_t st = sb + (c & 1) * G_STAGE;
        #pragma unroll
        for (int kk = 0; kk < 2; kk++) {
            uint32_t ah[2][4], al[2][4], bf[4][2];
            #pragma unroll
            for (int mi = 0; mi < 2; mi++) {
                const uint32_t ad = st + S_AH + a_l + mi * 16 * GRS + kk * 32;
                ldsm4(ah[mi], ad);
                ldsm4(al[mi], ad + (S_AL - S_AH));
            }
            #pragma unroll
            for (int np = 0; np < 2; np++) {
                uint32_t t[4];
                ldsm4(t, st + S_WH + b_l + np * 16 * GRS + kk * 32);
                bf[np * 2][0] = t[0]; bf[np * 2][1] = t[1];
                bf[np * 2 + 1][0] = t[2]; bf[np * 2 + 1][1] = t[3];
            }
            #pragma unroll
            for (int mi = 0; mi < 2; mi++)
                #pragma unroll
                for (int ni = 0; ni < 4; ni++) {
                    mma_f16(acc[mi][ni], ah[mi], bf[ni]);
                    mma_f16(acc[mi][ni], al[mi], bf[ni]);
                }
        }
        __syncthreads();
        if (c + 2 < 32) g_load(sb, Ah, Al, Wg, m0, n0, c + 2, tid);
    }
}

// -------- QKV projection: z selects q/k/v; writes fp16 per-head -------------
__global__ __launch_bounds__(256, 3) void qkv_gemm(const float* __restrict__ bias)
{
    extern __shared__ char sm[];
    const int z = blockIdx.z;
    const __half* Ah = g_inh + (size_t)z * NELEM;
    const __half* Al = g_inl + (size_t)z * NELEM;
    const __half* Wg = g_wih + (size_t)z * EMB * DM;
    const float* bz = bias + z * EMB;

    const int m0 = blockIdx.y * 128;
    const int n0 = blockIdx.x * 64;

    float acc[2][4][4];
    gemm_core(Ah, Al, Wg, m0, n0, su32(sm), acc);

    const int lane = threadIdx.x & 31, wid = threadIdx.x >> 5;
    const int mq = wid & 3, nh2 = wid >> 2;
    const int g = lane >> 2, t4 = lane & 3;

    #pragma unroll
    for (int mi = 0; mi < 2; mi++) {
        #pragma unroll
        for (int ni = 0; ni < 4; ni++) {
            const int mrow = m0 + mq * 32 + mi * 16 + g;
            const int ncol = n0 + nh2 * 32 + ni * 8 + t4 * 2;
            const float b0 = __ldg(&bz[ncol]), b1 = __ldg(&bz[ncol + 1]);
            const int h = ncol >> 6, d = ncol & 63;
            #pragma unroll
            for (int rr = 0; rr < 2; rr++) {
                const int m = mrow + rr * 8;
                const int t = m >> 1, b = m & 1;
                const float v0 = acc[mi][ni][rr * 2 + 0] + b0;
                const float v1 = acc[mi][ni][rr * 2 + 1] + b1;
                const size_t idx = ((size_t)(b * NH + h) * T_LEN + t) * HD + d;
                if (z == 0) {
                    uint32_t H, L;
                    fspl_pair(v0, v1, H, L);   // q unscaled; scale in softmax
                    *(uint32_t*)(g_qh + idx) = H;
                    *(uint32_t*)(g_ql + idx) = L;
                } else {
                    __half* dst = (z == 1) ? g_kh : g_vh;
                    *(uint32_t*)(dst + idx) = fpk(v0, v1);
                }
            }
        }
    }
}

// -------- Output projection: C = attn(fp16 hi/lo) @ Wo^T + bo ---------------
__global__ __launch_bounds__(256, 3) void out_gemm(const float* __restrict__ bias,
                                                   float* __restrict__ C)
{
    extern __shared__ char sm[];
    const int m0 = blockIdx.y * 128;
    const int n0 = blockIdx.x * 64;

    float acc[2][4][4];
    gemm_core(g_ah, g_al, g_woh, m0, n0, su32(sm), acc);

    const int lane = threadIdx.x & 31, wid = threadIdx.x >> 5;
    const int mq = wid & 3, nh2 = wid >> 2;
    const int g = lane >> 2, t4 = lane & 3;

    #pragma unroll
    for (int mi = 0; mi < 2; mi++) {
        #pragma unroll
        for (int ni = 0; ni < 4; ni++) {
            const int mrow = m0 + mq * 32 + mi * 16 + g;
            const int ncol = n0 + nh2 * 32 + ni * 8 + t4 * 2;
            const float b0 = __ldg(&bias[ncol]), b1 = __ldg(&bias[ncol + 1]);
            #pragma unroll
            for (int rr = 0; rr < 2; rr++) {
                const int m = mrow + rr * 8;
                float2 v;
                v.x = acc[mi][ni][rr * 2 + 0] + b0;
                v.y = acc[mi][ni][rr * 2 + 1] + b1;
                *(float2*)(C + (size_t)m * DM + ncol) = v;
            }
        }
    }
}

// ============================================================================
// Flash attention fp16 x2. CTA = 128 q-rows x one (b,h), 8 warps x 16 q-rows.
// Q hi/lo staged once; K/V single-fp16 tiles (64 keys) cp.async double-buffered.
// Scale 1/8 folded into softmax. Writes attn as fp16 hi/lo for out_gemm.
// ============================================================================
#define ARS 144
#define F_QH 0
#define F_QL 18432
#define F_KV 36864
#define F_KVS 18432          // per stage: KH 9216 + VH 9216
#define F_SMEM (F_KV + 2 * F_KVS)   // 73728

__device__ __forceinline__ void f_stage_kv(uint32_t sb, size_t hbase, int it, int tid)
{
    const uint32_t st = sb + F_KV + (it & 1) * F_KVS;
    const int s0 = it * 64;
    #pragma unroll
    for (int i = 0; i < 2; i++) {
        const int idx = tid + i * 256;
        const int row = idx >> 3, cc = idx & 7;
        const size_t src = (hbase + s0 + row) * HD + cc * 8;
        cpa(st + row * ARS + cc * 16, g_kh + src);
        cpa(st + 9216 + row * ARS + cc * 16, g_vh + src);
    }
    cp_commit();
}

__global__ __launch_bounds__(256, 2) void flash_mma(const float* __restrict__ mask)
{
    extern __shared__ char sm[];
    const uint32_t sb = su32(sm);
    const int tid = threadIdx.x, lane = tid & 31, w = tid >> 5;
    const int bh = blockIdx.y, qt = blockIdx.x;
    const int g = lane >> 2, t4 = lane & 3;
    const size_t hbase = (size_t)bh * T_LEN;

    // stage Q (hi+lo), then two K/V stages
    {
        const size_t qb = (hbase + qt * 128) * HD;
        #pragma unroll
        for (int i = 0; i < 4; i++) {
            const int idx = tid + i * 256;
            const int row = idx >> 3, cc = idx & 7;
            const size_t src = qb + (size_t)row * HD + cc * 8;
            cpa(sb + F_QH + row * ARS + cc * 16, g_qh + src);
            cpa(sb + F_QL + row * ARS + cc * 16, g_ql + src);
        }
        cp_commit();
    }
    f_stage_kv(sb, hbase, 0, tid);
    f_stage_kv(sb, hbase, 1, tid);
    cp_wait2();
    __syncthreads();

    uint32_t qh[4][4], ql[4][4];
    #pragma unroll
    for (int j = 0; j < 4; j++) {
        const uint32_t a = sb + F_QH + (w * 16 + (lane & 15)) * ARS +
                           (j * 16 + ((lane >> 4) << 3)) * 2;
        ldsm4(qh[j], a);
        ldsm4(ql[j], a + (F_QL - F_QH));
    }

    float oacc[8][4];
    #pragma unroll
    for (int i = 0; i < 8; i++)
        #pragma unroll
        for (int v = 0; v < 4; v++) oacc[i][v] = 0.f;
    float m0r = -1e30f, m1r = -1e30f, l0 = 0.f, l1 = 0.f;

    const int tq = qt * 128 + w * 16 + g;
    const float* mr0 = mask + (size_t)tq * T_LEN;
    const float* mr1 = mr0 + (size_t)8 * T_LEN;

    #pragma unroll 1
    for (int it = 0; it < 32; it++) {
        if (it == 31) cp_wait0(); else cp_wait1();
        __syncthreads();
        const uint32_t kst = sb + F_KV + (it & 1) * F_KVS;
        const uint32_t vst = kst + 9216;

        // ---- S = Q K^T (fp16 x2) ----
        float sacc[8][4];
        #pragma unroll
        for (int i = 0; i < 8; i++)
            #pragma unroll
            for (int v = 0; v < 4; v++) sacc[i][v] = 0.f;

        #pragma unroll
        for (int j = 0; j < 4; j++) {
            uint32_t kb[8][2];
            #pragma unroll
            for (int np = 0; np < 4; np++) {
                uint32_t t[4];
                ldsm4(t, kst + (np * 16 + ((lane >> 4) << 3) + (lane & 7)) * ARS +
                         (j * 16 + (lane & 8)) * 2);
                kb[np * 2][0] = t[0]; kb[np * 2][1] = t[1];
                kb[np * 2 + 1][0] = t[2]; kb[np * 2 + 1][1] = t[3];
            }
            #pragma unroll
            for (int jn = 0; jn < 8; jn++) {
                mma_f16(sacc[jn], qh[j], kb[jn]);
                mma_f16(sacc[jn], ql[j], kb[jn]);
            }
        }

        // ---- scale + mask + online softmax ----
        const int s0 = it * 64;
        float mx0 = -1e30f, mx1 = -1e30f;
        #pragma unroll
        for (int jn = 0; jn < 8; jn++) {
            const int sc = s0 + jn * 8 + t4 * 2;
            float2 ma = *(const float2*)(mr0 + sc);
            float2 mb = *(const float2*)(mr1 + sc);
            sacc[jn][0] = fmaf(sacc[jn][0], 0.125f, ma.x);
            sacc[jn][1] = fmaf(sacc[jn][1], 0.125f, ma.y);
            sacc[jn][2] = fmaf(sacc[jn][2], 0.125f, mb.x);
            sacc[jn][3] = fmaf(sacc[jn][3], 0.125f, mb.y);
            mx0 = fmaxf(mx0, fmaxf(sacc[jn][0], sacc[jn][1]));
            mx1 = fmaxf(mx1, fmaxf(sacc[jn][2], sacc[jn][3]));
        }
        mx0 = fmaxf(mx0, __shfl_xor_sync(0xffffffffu, mx0, 1));
        mx0 = fmaxf(mx0, __shfl_xor_sync(0xffffffffu, mx0, 2));
        mx1 = fmaxf(mx1, __shfl_xor_sync(0xffffffffu, mx1, 1));
        mx1 = fmaxf(mx1, __shfl_xor_sync(0xffffffffu, mx1, 2));

        const float mn0 = fmaxf(m0r, mx0), mn1 = fmaxf(m1r, mx1);
        const float c0 = __expf(m0r - mn0), c1 = __expf(m1r - mn1);
        m0r = mn0; m1r = mn1;
        l0 *= c0; l1 *= c1;
        #pragma unroll
        for (int jd = 0; jd < 8; jd++) {
            oacc[jd][0] *= c0; oacc[jd][1] *= c0;
            oacc[jd][2] *= c1; oacc[jd][3] *= c1;
        }
        #pragma unroll
        for (int jn = 0; jn < 8; jn++) {
            sacc[jn][0] = __expf(sacc[jn][0] - mn0);
            sacc[jn][1] = __expf(sacc[jn][1] - mn0);
            sacc[jn][2] = __expf(sacc[jn][2] - mn1);
            sacc[jn][3] = __expf(sacc[jn][3] - mn1);
            l0 += sacc[jn][0] + sacc[jn][1];
            l1 += sacc[jn][2] + sacc[jn][3];
        }

        // ---- O += P V (fp16 x2: P split, V single) ----
        #pragma unroll
        for (int js = 0; js < 4; js++) {
            uint32_t ph[4], pl[4];
            fspl_pair(sacc[2 * js][0], sacc[2 * js][1], ph[0], pl[0]);
            fspl_pair(sacc[2 * js][2], sacc[2 * js][3], ph[1], pl[1]);
            fspl_pair(sacc[2 * js + 1][0], sacc[2 * js + 1][1], ph[2], pl[2]);
            fspl_pair(sacc[2 * js + 1][2], sacc[2 * js + 1][3], ph[3], pl[3]);

            uint32_t vb[8][2];
            #pragma unroll
            for (int dp = 0; dp < 4; dp++) {
                uint32_t t[4];
                ldsm4t(t, vst + (js * 16 + (lane & 15)) * ARS +
                          (dp * 16 + ((lane >> 4) << 3)) * 2);
                vb[dp * 2][0] = t[0]; vb[dp * 2][1] = t[1];
                vb[dp * 2 + 1][0] = t[2]; vb[dp * 2 + 1][1] = t[3];
            }
            #pragma unroll
            for (int jd = 0; jd < 8; jd++) {
                mma_f16(oacc[jd], ph, vb[jd]);
                mma_f16(oacc[jd], pl, vb[jd]);
            }
        }
        __syncthreads();
        if (it + 2 < 32) f_stage_kv(sb, hbase, it + 2, tid);
    }

    l0 += __shfl_xor_sync(0xffffffffu, l0, 1);
    l0 += __shfl_xor_sync(0xffffffffu, l0, 2);
    l1 += __shfl_xor_sync(0xffffffffu, l1, 1);
    l1 += __shfl_xor_sync(0xffffffffu, l1, 2);
    const float i0 = 1.0f / l0, i1 = 1.0f / l1;

    const int b = bh >> 4, h = bh & 15;
    const size_t r0 = ((size_t)tq * BSZ + b) * EMB + h * HD;
    const size_t r1 = ((size_t)(tq + 8) * BSZ + b) * EMB + h * HD;
    #pragma unroll
    for (int jd = 0; jd < 8; jd++) {
        const int d = jd * 8 + t4 * 2;
        uint32_t H, L;
        fspl_pair(oacc[jd][0] * i0, oacc[jd][1] * i0, H, L);
        *(uint32_t*)(g_ah + r0 + d) = H;
        *(uint32_t*)(g_al + r0 + d) = L;
        fspl_pair(oacc[jd][2] * i1, oacc[jd][3] * i1, H, L);
        *(uint32_t*)(g_ah + r1 + d) = H;
        *(uint32_t*)(g_al + r1 + d) = L;
    }
}

// ============================================================================
// Launch
// ============================================================================
extern "C" void kernel_launch(void* const* d_in, const int* in_sizes, int n_in,
                              void* d_out, int out_size)
{
    const float* query  = (const float*)d_in[0];
    const float* key    = (const float*)d_in[1];
    const float* value  = (const float*)d_in[2];
    const float* mask   = (const float*)d_in[3];
    const float* in_w   = (const float*)d_in[4];
    const float* in_b   = (const float*)d_in[5];
    const float* out_w  = (const float*)d_in[6];
    const float* out_b  = (const float*)d_in[7];
    float* out = (float*)d_out;

    cudaFuncSetAttribute(qkv_gemm, cudaFuncAttributeMaxDynamicSharedMemorySize, G_SMEM);
    cudaFuncSetAttribute(out_gemm, cudaFuncAttributeMaxDynamicSharedMemorySize, G_SMEM);
    cudaFuncSetAttribute(flash_mma, cudaFuncAttributeMaxDynamicSharedMemorySize, F_SMEM);

    // 0) prep: split inputs to fp16 hi/lo; convert weights to fp16
    prep_split<<<dim3(NELEM / 1024, 3), 256>>>(query, key, value);
    prep_cvt<<<(3 * EMB * DM) / 1024, 256>>>(in_w, 0, 3 * EMB * DM);
    prep_cvt<<<(DM * EMB) / 1024, 256>>>(out_w, 1, DM * EMB);

    // 1) QKV projection (fp16 x2 mma), scatter to per-head fp16 layout
    qkv_gemm<<<dim3(EMB / 64, MROWS / 128, 3), 256, G_SMEM>>>(in_b);

    // 2) Attention (fp16 x2 flash) -> attn fp16 hi/lo
    flash_mma<<<dim3(T_LEN / 128, BSZ * NH), 256, F_SMEM>>>(mask);

    // 3) Output projection (fp16 x2 mma) -> d_out
    out_gemm<<<dim3(DM / 64, MROWS / 128), 256, G_SMEM>>>(out_b, out);
}

// round 6
// speedup vs baseline: 4.9943x; 1.1104x over previous
#include <cuda_runtime.h>
#include <cuda_fp16.h>
#include <cstdint>

#define T_LEN 2048
#define BSZ   2
#define DM    1024
#define NH    16
#define HD    64
#define EMB   1024
#define MROWS 4096
#define NELEM ((size_t)MROWS * DM)          // 4M elements per input tensor

// ---------------- scratch (allocation-free: device globals) ----------------
__device__ __half g_inh[3 * NELEM];         // inputs split hi (q,k,v)
__device__ __half g_inl[3 * NELEM];         // inputs split lo
__device__ __half g_wih[(size_t)3 * EMB * DM];  // in_proj_weight fp16
__device__ __half g_woh[(size_t)DM * EMB];      // out_proj_weight fp16
__device__ __half g_qh[(size_t)BSZ * NH * T_LEN * HD];  // q hi (pre-scaled by 1/8)
__device__ __half g_ql[(size_t)BSZ * NH * T_LEN * HD];  // q lo
__device__ __half g_kh[(size_t)BSZ * NH * T_LEN * HD];  // k fp16
__device__ __half g_vh[(size_t)BSZ * NH * T_LEN * HD];  // v fp16
__device__ __half g_ah[NELEM];              // attn out hi  [t*B+b][e]
__device__ __half g_al[NELEM];              // attn out lo
__device__ int g_mask_nz;                   // 1 if mask has any nonzero

// ============================ PTX helpers ===================================
__device__ __forceinline__ uint32_t su32(const void* p) {
    uint32_t a;
    asm("{ .reg .u64 t; cvta.to.shared.u64 t, %1; cvt.u32.u64 %0, t; }"
        : "=r"(a) : "l"(p));
    return a;
}
__device__ __forceinline__ void cpa(uint32_t s, const void* g) {
    asm volatile("cp.async.cg.shared.global [%0], [%1], 16;" :: "r"(s), "l"(g));
}
__device__ __forceinline__ void cp_commit() {
    asm volatile("cp.async.commit_group;" ::: "memory");
}
__device__ __forceinline__ void cp_wait0() {
    asm volatile("cp.async.wait_group 0;" ::: "memory");
}
__device__ __forceinline__ void cp_wait1() {
    asm volatile("cp.async.wait_group 1;" ::: "memory");
}
__device__ __forceinline__ void cp_wait2() {
    asm volatile("cp.async.wait_group 2;" ::: "memory");
}
__device__ __forceinline__ void ldsm4(uint32_t r[4], uint32_t a) {
    asm volatile("ldmatrix.sync.aligned.m8n8.x4.shared.b16 {%0,%1,%2,%3}, [%4];"
                 : "=r"(r[0]), "=r"(r[1]), "=r"(r[2]), "=r"(r[3]) : "r"(a));
}
__device__ __forceinline__ void ldsm4t(uint32_t r[4], uint32_t a) {
    asm volatile("ldmatrix.sync.aligned.m8n8.x4.trans.shared.b16 {%0,%1,%2,%3}, [%4];"
                 : "=r"(r[0]), "=r"(r[1]), "=r"(r[2]), "=r"(r[3]) : "r"(a));
}
__device__ __forceinline__ void mma_f16(float c[4], const uint32_t a[4],
                                        const uint32_t b[2]) {
    asm volatile(
        "mma.sync.aligned.m16n8k16.row.col.f32.f16.f16.f32 "
        "{%0,%1,%2,%3}, {%4,%5,%6,%7}, {%8,%9}, {%0,%1,%2,%3};"
        : "+f"(c[0]), "+f"(c[1]), "+f"(c[2]), "+f"(c[3])
        : "r"(a[0]), "r"(a[1]), "r"(a[2]), "r"(a[3]), "r"(b[0]), "r"(b[1]));
}

// ---------------- fp16 split helpers ----------------------------------------
__device__ __forceinline__ void fspl1(float x, uint16_t& h, float& r) {
    __half hb = __float2half_rn(x);
    r = x - __half2float(hb);
    h = __half_as_ushort(hb);
}
__device__ __forceinline__ uint32_t fpk(float a, float b) {
    __half2 t = __floats2half2_rn(a, b);
    return *reinterpret_cast<uint32_t*>(&t);
}
__device__ __forceinline__ void fspl_pair(float x0, float x1,
                                          uint32_t& H, uint32_t& L) {
    uint16_t h0, h1; float r0, r1;
    fspl1(x0, h0, r0); fspl1(x1, h1, r1);
    H = (uint32_t)h0 | ((uint32_t)h1 << 16);
    L = fpk(r0, r1);
}

// ============================================================================
// Prep kernels
// ============================================================================
__global__ __launch_bounds__(256) void prep_split(
    const float* __restrict__ q, const float* __restrict__ k,
    const float* __restrict__ v)
{
    if (blockIdx.x == 0 && blockIdx.y == 0 && threadIdx.x == 0) g_mask_nz = 0;
    const int z = blockIdx.y;
    const float* s = (z == 0) ? q : (z == 1) ? k : v;
    __half* dh = g_inh + (size_t)z * NELEM;
    __half* dl = g_inl + (size_t)z * NELEM;
    const size_t i = ((size_t)blockIdx.x * 256 + threadIdx.x) * 4;
    float4 x = *(const float4*)(s + i);
    uint16_t h0, h1, h2, h3; float r0, r1, r2, r3;
    fspl1(x.x, h0, r0); fspl1(x.y, h1, r1);
    fspl1(x.z, h2, r2); fspl1(x.w, h3, r3);
    uint2 H, L;
    H.x = (uint32_t)h0 | ((uint32_t)h1 << 16);
    H.y = (uint32_t)h2 | ((uint32_t)h3 << 16);
    L.x = fpk(r0, r1); L.y = fpk(r2, r3);
    *(uint2*)(dh + i) = H;
    *(uint2*)(dl + i) = L;
}

__global__ __launch_bounds__(256) void prep_cvt(const float* __restrict__ s,
                                                int which, int n)
{
    __half* d = which ? g_woh : g_wih;
    const int i = (blockIdx.x * 256 + threadIdx.x) * 4;
    if (i < n) {
        float4 x = *(const float4*)(s + i);
        uint2 H;
        H.x = fpk(x.x, x.y);
        H.y = fpk(x.z, x.w);
        *(uint2*)(d + i) = H;
    }
}

__global__ __launch_bounds__(256) void mask_scan(const float* __restrict__ m)
{
    const size_t i = ((size_t)blockIdx.x * 256 + threadIdx.x) * 4;
    float4 v = *(const float4*)(m + i);
    if (v.x != 0.f || v.y != 0.f || v.z != 0.f || v.w != 0.f) g_mask_nz = 1;
}

// ============================================================================
// GEMM core (TN, fp16 x2): CTA 128x128, chunk K=32, cp.async double-buffered.
// smem/stage: Ah[128x32] Al Wh[128x32] fp16, row stride 80B.
// 8 warps = 2(m) x 4(n); warp tile 64x32 -> acc[4][4][4].
// ============================================================================
#define GRS 80
#define S_AH 0
#define S_AL 10240
#define S_WH 20480
#define G_STAGE 30720
#define G_SMEM (2 * G_STAGE)

__device__ __forceinline__ void g_load(uint32_t sb, const __half* Ah,
                                       const __half* Al, const __half* Wg,
                                       int m0, int n0, int c, int tid)
{
    const uint32_t st = sb + (c & 1) * G_STAGE;
    const int k0 = c * 32;
    #pragma unroll
    for (int i = 0; i < 2; i++) {
        const int idx = tid + i * 256;          // 0..511
        const int row = idx >> 2, cc = idx & 3;
        const uint32_t o = row * GRS + cc * 16;
        const size_t srcA = (size_t)(m0 + row) * DM + k0 + cc * 8;
        cpa(st + S_AH + o, Ah + srcA);
        cpa(st + S_AL + o, Al + srcA);
        cpa(st + S_WH + o, Wg + (size_t)(n0 + row) * DM + k0 + cc * 8);
    }
    cp_commit();
}

__device__ __forceinline__ void gemm_core(
    const __half* __restrict__ Ah, const __half* __restrict__ Al,
    const __half* __restrict__ Wg, int m0, int n0, uint32_t sb,
    float (&acc)[4][4][4])
{
    const int tid = threadIdx.x, lane = tid & 31, wid = tid >> 5;
    const int mh = wid & 1;          // 0..1 : 64-row half
    const int nq = wid >> 1;         // 0..3 : 32-col quad

    #pragma unroll
    for (int i = 0; i < 4; i++)
        #pragma unroll
        for (int j = 0; j < 4; j++)
            #pragma unroll
            for (int v = 0; v < 4; v++) acc[i][j][v] = 0.f;

    g_load(sb, Ah, Al, Wg, m0, n0, 0, tid);
    g_load(sb, Ah, Al, Wg, m0, n0, 1, tid);

    const int a_l = (mh * 64 + (lane & 15)) * GRS + ((lane >> 4) << 3) * 2;
    const int b_l = (nq * 32 + ((lane >> 4) << 3) + (lane & 7)) * GRS + (lane & 8) * 2;

    for (int c = 0; c < 32; c++) {
        if (c == 31) cp_wait0(); else cp_wait1();
        __syncthreads();
        const uint32_t st = sb + (c & 1) * G_STAGE;
        #pragma unroll
        for (int kk = 0; kk < 2; kk++) {
            uint32_t ah[4][4], al[4][4], bf[4][2];
            #pragma unroll
            for (int mi = 0; mi < 4; mi++) {
                const uint32_t ad = st + S_AH + a_l + mi * 16 * GRS + kk * 32;
                ldsm4(ah[mi], ad);
                ldsm4(al[mi], ad + (S_AL - S_AH));
            }
            #pragma unroll
            for (int np = 0; np < 2; np++) {
                uint32_t t[4];
                ldsm4(t, st + S_WH + b_l + np * 16 * GRS + kk * 32);
                bf[np * 2][0] = t[0]; bf[np * 2][1] = t[1];
                bf[np * 2 + 1][0] = t[2]; bf[np * 2 + 1][1] = t[3];
            }
            #pragma unroll
            for (int mi = 0; mi < 4; mi++)
                #pragma unroll
                for (int ni = 0; ni < 4; ni++) {
                    mma_f16(acc[mi][ni], ah[mi], bf[ni]);
                    mma_f16(acc[mi][ni], al[mi], bf[ni]);
                }
        }
        __syncthreads();
        if (c + 2 < 32) g_load(sb, Ah, Al, Wg, m0, n0, c + 2, tid);
    }
}

// -------- QKV projection: z selects q/k/v; writes fp16 per-head -------------
__global__ __launch_bounds__(256, 2) void qkv_gemm(const float* __restrict__ bias)
{
    extern __shared__ char sm[];
    const int z = blockIdx.z;
    const __half* Ah = g_inh + (size_t)z * NELEM;
    const __half* Al = g_inl + (size_t)z * NELEM;
    const __half* Wg = g_wih + (size_t)z * EMB * DM;
    const float* bz = bias + z * EMB;

    const int m0 = blockIdx.y * 128;
    const int n0 = blockIdx.x * 128;

    float acc[4][4][4];
    gemm_core(Ah, Al, Wg, m0, n0, su32(sm), acc);

    const int lane = threadIdx.x & 31, wid = threadIdx.x >> 5;
    const int mh = wid & 1, nq = wid >> 1;
    const int g = lane >> 2, t4 = lane & 3;

    #pragma unroll
    for (int mi = 0; mi < 4; mi++) {
        #pragma unroll
        for (int ni = 0; ni < 4; ni++) {
            const int mrow = m0 + mh * 64 + mi * 16 + g;
            const int ncol = n0 + nq * 32 + ni * 8 + t4 * 2;
            const float b0 = __ldg(&bz[ncol]), b1 = __ldg(&bz[ncol + 1]);
            const int h = ncol >> 6, d = ncol & 63;
            #pragma unroll
            for (int rr = 0; rr < 2; rr++) {
                const int m = mrow + rr * 8;
                const int t = m >> 1, b = m & 1;
                float v0 = acc[mi][ni][rr * 2 + 0] + b0;
                float v1 = acc[mi][ni][rr * 2 + 1] + b1;
                const size_t idx = ((size_t)(b * NH + h) * T_LEN + t) * HD + d;
                if (z == 0) {
                    v0 *= 0.125f; v1 *= 0.125f;   // fold HD^-0.5 into q (exact)
                    uint32_t H, L;
                    fspl_pair(v0, v1, H, L);
                    *(uint32_t*)(g_qh + idx) = H;
                    *(uint32_t*)(g_ql + idx) = L;
                } else {
                    __half* dst = (z == 1) ? g_kh : g_vh;
                    *(uint32_t*)(dst + idx) = fpk(v0, v1);
                }
            }
        }
    }
}

// -------- Output projection: C = attn(fp16 hi/lo) @ Wo^T + bo ---------------
__global__ __launch_bounds__(256, 2) void out_gemm(const float* __restrict__ bias,
                                                   float* __restrict__ C)
{
    extern __shared__ char sm[];
    const int m0 = blockIdx.y * 128;
    const int n0 = blockIdx.x * 128;

    float acc[4][4][4];
    gemm_core(g_ah, g_al, g_woh, m0, n0, su32(sm), acc);

    const int lane = threadIdx.x & 31, wid = threadIdx.x >> 5;
    const int mh = wid & 1, nq = wid >> 1;
    const int g = lane >> 2, t4 = lane & 3;

    #pragma unroll
    for (int mi = 0; mi < 4; mi++) {
        #pragma unroll
        for (int ni = 0; ni < 4; ni++) {
            const int mrow = m0 + mh * 64 + mi * 16 + g;
            const int ncol = n0 + nq * 32 + ni * 8 + t4 * 2;
            const float b0 = __ldg(&bias[ncol]), b1 = __ldg(&bias[ncol + 1]);
            #pragma unroll
            for (int rr = 0; rr < 2; rr++) {
                const int m = mrow + rr * 8;
                float2 v;
                v.x = acc[mi][ni][rr * 2 + 0] + b0;
                v.y = acc[mi][ni][rr * 2 + 1] + b1;
                *(float2*)(C + (size_t)m * DM + ncol) = v;
            }
        }
    }
}

// ============================================================================
// Flash attention fp16 x2. CTA = 128 q-rows x one (b,h), 8 warps x 16 q-rows.
// Q hi/lo staged once; K/V single-fp16 tiles (64 keys) cp.async double-buffered.
// q pre-scaled by 1/8. Mask applied only if g_mask_nz (flag from mask_scan).
// ============================================================================
#define ARS 144
#define F_QH 0
#define F_QL 18432
#define F_KV 36864
#define F_KVS 18432          // per stage: KH 9216 + VH 9216
#define F_SMEM (F_KV + 2 * F_KVS)   // 73728

__device__ __forceinline__ void f_stage_kv(uint32_t sb, size_t hbase, int it, int tid)
{
    const uint32_t st = sb + F_KV + (it & 1) * F_KVS;
    const int s0 = it * 64;
    #pragma unroll
    for (int i = 0; i < 2; i++) {
        const int idx = tid + i * 256;
        const int row = idx >> 3, cc = idx & 7;
        const size_t src = (hbase + s0 + row) * HD + cc * 8;
        cpa(st + row * ARS + cc * 16, g_kh + src);
        cpa(st + 9216 + row * ARS + cc * 16, g_vh + src);
    }
    cp_commit();
}

__global__ __launch_bounds__(256, 2) void flash_mma(const float* __restrict__ mask)
{
    extern __shared__ char sm[];
    const uint32_t sb = su32(sm);
    const int tid = threadIdx.x, lane = tid & 31, w = tid >> 5;
    const int bh = blockIdx.y, qt = blockIdx.x;
    const int g = lane >> 2, t4 = lane & 3;
    const size_t hbase = (size_t)bh * T_LEN;
    const int mnz = g_mask_nz;

    {
        const size_t qb = (hbase + qt * 128) * HD;
        #pragma unroll
        for (int i = 0; i < 4; i++) {
            const int idx = tid + i * 256;
            const int row = idx >> 3, cc = idx & 7;
            const size_t src = qb + (size_t)row * HD + cc * 8;
            cpa(sb + F_QH + row * ARS + cc * 16, g_qh + src);
            cpa(sb + F_QL + row * ARS + cc * 16, g_ql + src);
        }
        cp_commit();
    }
    f_stage_kv(sb, hbase, 0, tid);
    f_stage_kv(sb, hbase, 1, tid);
    cp_wait2();
    __syncthreads();

    uint32_t qh[4][4], ql[4][4];
    #pragma unroll
    for (int j = 0; j < 4; j++) {
        const uint32_t a = sb + F_QH + (w * 16 + (lane & 15)) * ARS +
                           (j * 16 + ((lane >> 4) << 3)) * 2;
        ldsm4(qh[j], a);
        ldsm4(ql[j], a + (F_QL - F_QH));
    }

    float oacc[8][4];
    #pragma unroll
    for (int i = 0; i < 8; i++)
        #pragma unroll
        for (int v = 0; v < 4; v++) oacc[i][v] = 0.f;
    float m0r = -1e30f, m1r = -1e30f, l0 = 0.f, l1 = 0.f;

    const int tq = qt * 128 + w * 16 + g;
    const float* mr0 = mask + (size_t)tq * T_LEN;
    const float* mr1 = mr0 + (size_t)8 * T_LEN;

    #pragma unroll 1
    for (int it = 0; it < 32; it++) {
        if (it == 31) cp_wait0(); else cp_wait1();
        __syncthreads();
        const uint32_t kst = sb + F_KV + (it & 1) * F_KVS;
        const uint32_t vst = kst + 9216;

        // ---- S = Q K^T (fp16 x2; q pre-scaled) ----
        float sacc[8][4];
        #pragma unroll
        for (int i = 0; i < 8; i++)
            #pragma unroll
            for (int v = 0; v < 4; v++) sacc[i][v] = 0.f;

        #pragma unroll
        for (int j = 0; j < 4; j++) {
            uint32_t kb[8][2];
            #pragma unroll
            for (int np = 0; np < 4; np++) {
                uint32_t t[4];
                ldsm4(t, kst + (np * 16 + ((lane >> 4) << 3) + (lane & 7)) * ARS +
                         (j * 16 + (lane & 8)) * 2);
                kb[np * 2][0] = t[0]; kb[np * 2][1] = t[1];
                kb[np * 2 + 1][0] = t[2]; kb[np * 2 + 1][1] = t[3];
            }
            #pragma unroll
            for (int jn = 0; jn < 8; jn++) {
                mma_f16(sacc[jn], qh[j], kb[jn]);
                mma_f16(sacc[jn], ql[j], kb[jn]);
            }
        }

        // ---- optional mask + online softmax ----
        const int s0 = it * 64;
        if (mnz) {
            #pragma unroll
            for (int jn = 0; jn < 8; jn++) {
                const int sc = s0 + jn * 8 + t4 * 2;
                float2 ma = *(const float2*)(mr0 + sc);
                float2 mb = *(const float2*)(mr1 + sc);
                sacc[jn][0] += ma.x; sacc[jn][1] += ma.y;
                sacc[jn][2] += mb.x; sacc[jn][3] += mb.y;
            }
        }
        float mx0 = -1e30f, mx1 = -1e30f;
        #pragma unroll
        for (int jn = 0; jn < 8; jn++) {
            mx0 = fmaxf(mx0, fmaxf(sacc[jn][0], sacc[jn][1]));
            mx1 = fmaxf(mx1, fmaxf(sacc[jn][2], sacc[jn][3]));
        }
        mx0 = fmaxf(mx0, __shfl_xor_sync(0xffffffffu, mx0, 1));
        mx0 = fmaxf(mx0, __shfl_xor_sync(0xffffffffu, mx0, 2));
        mx1 = fmaxf(mx1, __shfl_xor_sync(0xffffffffu, mx1, 1));
        mx1 = fmaxf(mx1, __shfl_xor_sync(0xffffffffu, mx1, 2));

        const float mn0 = fmaxf(m0r, mx0), mn1 = fmaxf(m1r, mx1);
        const float c0 = __expf(m0r - mn0), c1 = __expf(m1r - mn1);
        m0r = mn0; m1r = mn1;
        l0 *= c0; l1 *= c1;
        #pragma unroll
        for (int jd = 0; jd < 8; jd++) {
            oacc[jd][0] *= c0; oacc[jd][1] *= c0;
            oacc[jd][2] *= c1; oacc[jd][3] *= c1;
        }
        #pragma unroll
        for (int jn = 0; jn < 8; jn++) {
            sacc[jn][0] = __expf(sacc[jn][0] - mn0);
            sacc[jn][1] = __expf(sacc[jn][1] - mn0);
            sacc[jn][2] = __expf(sacc[jn][2] - mn1);
            sacc[jn][3] = __expf(sacc[jn][3] - mn1);
            l0 += sacc[jn][0] + sacc[jn][1];
            l1 += sacc[jn][2] + sacc[jn][3];
        }

        // ---- O += P V (fp16 x2: P split, V single) ----
        #pragma unroll
        for (int js = 0; js < 4; js++) {
            uint32_t ph[4], pl[4];
            fspl_pair(sacc[2 * js][0], sacc[2 * js][1], ph[0], pl[0]);
            fspl_pair(sacc[2 * js][2], sacc[2 * js][3], ph[1], pl[1]);
            fspl_pair(sacc[2 * js + 1][0], sacc[2 * js + 1][1], ph[2], pl[2]);
            fspl_pair(sacc[2 * js + 1][2], sacc[2 * js + 1][3], ph[3], pl[3]);

            uint32_t vb[8][2];
            #pragma unroll
            for (int dp = 0; dp < 4; dp++) {
                uint32_t t[4];
                ldsm4t(t, vst + (js * 16 + (lane & 15)) * ARS +
                          (dp * 16 + ((lane >> 4) << 3)) * 2);
                vb[dp * 2][0] = t[0]; vb[dp * 2][1] = t[1];
                vb[dp * 2 + 1][0] = t[2]; vb[dp * 2 + 1][1] = t[3];
            }
            #pragma unroll
            for (int jd = 0; jd < 8; jd++) {
                mma_f16(oacc[jd], ph, vb[jd]);
                mma_f16(oacc[jd], pl, vb[jd]);
            }
        }
        __syncthreads();
        if (it + 2 < 32) f_stage_kv(sb, hbase, it + 2, tid);
    }

    l0 += __shfl_xor_sync(0xffffffffu, l0, 1);
    l0 += __shfl_xor_sync(0xffffffffu, l0, 2);
    l1 += __shfl_xor_sync(0xffffffffu, l1, 1);
    l1 += __shfl_xor_sync(0xffffffffu, l1, 2);
    const float i0 = 1.0f / l0, i1 = 1.0f / l1;

    const int b = bh >> 4, h = bh & 15;
    const size_t r0 = ((size_t)tq * BSZ + b) * EMB + h * HD;
    const size_t r1 = ((size_t)(tq + 8) * BSZ + b) * EMB + h * HD;
    #pragma unroll
    for (int jd = 0; jd < 8; jd++) {
        const int d = jd * 8 + t4 * 2;
        uint32_t H, L;
        fspl_pair(oacc[jd][0] * i0, oacc[jd][1] * i0, H, L);
        *(uint32_t*)(g_ah + r0 + d) = H;
        *(uint32_t*)(g_al + r0 + d) = L;
        fspl_pair(oacc[jd][2] * i1, oacc[jd][3] * i1, H, L);
        *(uint32_t*)(g_ah + r1 + d) = H;
        *(uint32_t*)(g_al + r1 + d) = L;
    }
}

// ============================================================================
// Launch
// ============================================================================
extern "C" void kernel_launch(void* const* d_in, const int* in_sizes, int n_in,
                              void* d_out, int out_size)
{
    const float* query  = (const float*)d_in[0];
    const float* key    = (const float*)d_in[1];
    const float* value  = (const float*)d_in[2];
    const float* mask   = (const float*)d_in[3];
    const float* in_w   = (const float*)d_in[4];
    const float* in_b   = (const float*)d_in[5];
    const float* out_w  = (const float*)d_in[6];
    const float* out_b  = (const float*)d_in[7];
    float* out = (float*)d_out;

    cudaFuncSetAttribute(qkv_gemm, cudaFuncAttributeMaxDynamicSharedMemorySize, G_SMEM);
    cudaFuncSetAttribute(out_gemm, cudaFuncAttributeMaxDynamicSharedMemorySize, G_SMEM);
    cudaFuncSetAttribute(flash_mma, cudaFuncAttributeMaxDynamicSharedMemorySize, F_SMEM);

    // 0) prep: split inputs; convert weights; scan mask for nonzeros
    prep_split<<<dim3(NELEM / 1024, 3), 256>>>(query, key, value);
    mask_scan<<<(T_LEN * T_LEN) / 1024, 256>>>(mask);
    prep_cvt<<<(3 * EMB * DM) / 1024, 256>>>(in_w, 0, 3 * EMB * DM);
    prep_cvt<<<(DM * EMB) / 1024, 256>>>(out_w, 1, DM * EMB);

    // 1) QKV projection (fp16 x2 mma, 128x128 tiles)
    qkv_gemm<<<dim3(EMB / 128, MROWS / 128, 3), 256, G_SMEM>>>(in_b);

    // 2) Attention (fp16 x2 flash, mask fast-path)
    flash_mma<<<dim3(T_LEN / 128, BSZ * NH), 256, F_SMEM>>>(mask);

    // 3) Output projection (fp16 x2 mma) -> d_out
    out_gemm<<<dim3(DM / 128, MROWS / 128), 256, G_SMEM>>>(out_b, out);
}

// round 7
// speedup vs baseline: 6.0152x; 1.2044x over previous
#include <cuda_runtime.h>
#include <cuda_fp16.h>
#include <cstdint>

#define T_LEN 2048
#define BSZ   2
#define DM    1024
#define NH    16
#define HD    64
#define EMB   1024
#define MROWS 4096
#define NELEM ((size_t)MROWS * DM)          // 4M elements per input tensor

// ---------------- scratch (allocation-free: device globals) ----------------
__device__ __half g_inh[3 * NELEM];         // inputs split hi (q,k,v)
__device__ __half g_inl[3 * NELEM];         // inputs split lo
__device__ __half g_wih[(size_t)3 * EMB * DM];  // in_proj_weight fp16
__device__ __half g_woh[(size_t)DM * EMB];      // out_proj_weight fp16
__device__ __half g_qh[(size_t)BSZ * NH * T_LEN * HD];  // q fp16 (pre-scaled 1/8)
__device__ __half g_kh[(size_t)BSZ * NH * T_LEN * HD];  // k fp16
__device__ __half g_vh[(size_t)BSZ * NH * T_LEN * HD];  // v fp16
__device__ __half g_ah[NELEM];              // attn out hi  [t*B+b][e]
__device__ __half g_al[NELEM];              // attn out lo
__device__ int g_mask_nz;                   // 1 if mask has any nonzero

// ============================ PTX helpers ===================================
__device__ __forceinline__ uint32_t su32(const void* p) {
    uint32_t a;
    asm("{ .reg .u64 t; cvta.to.shared.u64 t, %1; cvt.u32.u64 %0, t; }"
        : "=r"(a) : "l"(p));
    return a;
}
__device__ __forceinline__ void cpa(uint32_t s, const void* g) {
    asm volatile("cp.async.cg.shared.global [%0], [%1], 16;" :: "r"(s), "l"(g));
}
__device__ __forceinline__ void cp_commit() {
    asm volatile("cp.async.commit_group;" ::: "memory");
}
__device__ __forceinline__ void cp_wait0() {
    asm volatile("cp.async.wait_group 0;" ::: "memory");
}
__device__ __forceinline__ void cp_wait1() {
    asm volatile("cp.async.wait_group 1;" ::: "memory");
}
__device__ __forceinline__ void cp_wait2() {
    asm volatile("cp.async.wait_group 2;" ::: "memory");
}
__device__ __forceinline__ void ldsm4(uint32_t r[4], uint32_t a) {
    asm volatile("ldmatrix.sync.aligned.m8n8.x4.shared.b16 {%0,%1,%2,%3}, [%4];"
                 : "=r"(r[0]), "=r"(r[1]), "=r"(r[2]), "=r"(r[3]) : "r"(a));
}
__device__ __forceinline__ void ldsm4t(uint32_t r[4], uint32_t a) {
    asm volatile("ldmatrix.sync.aligned.m8n8.x4.trans.shared.b16 {%0,%1,%2,%3}, [%4];"
                 : "=r"(r[0]), "=r"(r[1]), "=r"(r[2]), "=r"(r[3]) : "r"(a));
}
__device__ __forceinline__ void mma_f16(float c[4], const uint32_t a[4],
                                        const uint32_t b[2]) {
    asm volatile(
        "mma.sync.aligned.m16n8k16.row.col.f32.f16.f16.f32 "
        "{%0,%1,%2,%3}, {%4,%5,%6,%7}, {%8,%9}, {%0,%1,%2,%3};"
        : "+f"(c[0]), "+f"(c[1]), "+f"(c[2]), "+f"(c[3])
        : "r"(a[0]), "r"(a[1]), "r"(a[2]), "r"(a[3]), "r"(b[0]), "r"(b[1]));
}

// ---------------- fp16 split helpers ----------------------------------------
__device__ __forceinline__ void fspl1(float x, uint16_t& h, float& r) {
    __half hb = __float2half_rn(x);
    r = x - __half2float(hb);
    h = __half_as_ushort(hb);
}
__device__ __forceinline__ uint32_t fpk(float a, float b) {
    __half2 t = __floats2half2_rn(a, b);
    return *reinterpret_cast<uint32_t*>(&t);
}
__device__ __forceinline__ void fspl_pair(float x0, float x1,
                                          uint32_t& H, uint32_t& L) {
    uint16_t h0, h1; float r0, r1;
    fspl1(x0, h0, r0); fspl1(x1, h1, r1);
    H = (uint32_t)h0 | ((uint32_t)h1 << 16);
    L = fpk(r0, r1);
}

// ============================================================================
// Prep kernels
// ============================================================================
__global__ __launch_bounds__(256) void prep_split(
    const float* __restrict__ q, const float* __restrict__ k,
    const float* __restrict__ v)
{
    if (blockIdx.x == 0 && blockIdx.y == 0 && threadIdx.x == 0) g_mask_nz = 0;
    const int z = blockIdx.y;
    const float* s = (z == 0) ? q : (z == 1) ? k : v;
    __half* dh = g_inh + (size_t)z * NELEM;
    __half* dl = g_inl + (size_t)z * NELEM;
    const size_t i = ((size_t)blockIdx.x * 256 + threadIdx.x) * 4;
    float4 x = *(const float4*)(s + i);
    uint16_t h0, h1, h2, h3; float r0, r1, r2, r3;
    fspl1(x.x, h0, r0); fspl1(x.y, h1, r1);
    fspl1(x.z, h2, r2); fspl1(x.w, h3, r3);
    uint2 H, L;
    H.x = (uint32_t)h0 | ((uint32_t)h1 << 16);
    H.y = (uint32_t)h2 | ((uint32_t)h3 << 16);
    L.x = fpk(r0, r1); L.y = fpk(r2, r3);
    *(uint2*)(dh + i) = H;
    *(uint2*)(dl + i) = L;
}

__global__ __launch_bounds__(256) void prep_cvt(const float* __restrict__ s,
                                                int which, int n)
{
    __half* d = which ? g_woh : g_wih;
    const int i = (blockIdx.x * 256 + threadIdx.x) * 4;
    if (i < n) {
        float4 x = *(const float4*)(s + i);
        uint2 H;
        H.x = fpk(x.x, x.y);
        H.y = fpk(x.z, x.w);
        *(uint2*)(d + i) = H;
    }
}

__global__ __launch_bounds__(256) void mask_scan(const float* __restrict__ m)
{
    const size_t i = ((size_t)blockIdx.x * 256 + threadIdx.x) * 4;
    float4 v = *(const float4*)(m + i);
    if (v.x != 0.f || v.y != 0.f || v.z != 0.f || v.w != 0.f) g_mask_nz = 1;
}

// ============================================================================
// GEMM core (TN, fp16 x2): CTA 128x128, chunk K=32, cp.async double-buffered.
// smem/stage: Ah[128x32] Al Wh[128x32] fp16, row stride 80B.
// 8 warps = 2(m) x 4(n); warp tile 64x32 -> acc[4][4][4].
// ============================================================================
#define GRS 80
#define S_AH 0
#define S_AL 10240
#define S_WH 20480
#define G_STAGE 30720
#define G_SMEM (2 * G_STAGE)

__device__ __forceinline__ void g_load(uint32_t sb, const __half* Ah,
                                       const __half* Al, const __half* Wg,
                                       int m0, int n0, int c, int tid)
{
    const uint32_t st = sb + (c & 1) * G_STAGE;
    const int k0 = c * 32;
    #pragma unroll
    for (int i = 0; i < 2; i++) {
        const int idx = tid + i * 256;          // 0..511
        const int row = idx >> 2, cc = idx & 3;
        const uint32_t o = row * GRS + cc * 16;
        const size_t srcA = (size_t)(m0 + row) * DM + k0 + cc * 8;
        cpa(st + S_AH + o, Ah + srcA);
        cpa(st + S_AL + o, Al + srcA);
        cpa(st + S_WH + o, Wg + (size_t)(n0 + row) * DM + k0 + cc * 8);
    }
    cp_commit();
}

__device__ __forceinline__ void gemm_core(
    const __half* __restrict__ Ah, const __half* __restrict__ Al,
    const __half* __restrict__ Wg, int m0, int n0, uint32_t sb,
    float (&acc)[4][4][4])
{
    const int tid = threadIdx.x, lane = tid & 31, wid = tid >> 5;
    const int mh = wid & 1;          // 0..1 : 64-row half
    const int nq = wid >> 1;         // 0..3 : 32-col quad

    #pragma unroll
    for (int i = 0; i < 4; i++)
        #pragma unroll
        for (int j = 0; j < 4; j++)
            #pragma unroll
            for (int v = 0; v < 4; v++) acc[i][j][v] = 0.f;

    g_load(sb, Ah, Al, Wg, m0, n0, 0, tid);
    g_load(sb, Ah, Al, Wg, m0, n0, 1, tid);

    const int a_l = (mh * 64 + (lane & 15)) * GRS + ((lane >> 4) << 3) * 2;
    const int b_l = (nq * 32 + ((lane >> 4) << 3) + (lane & 7)) * GRS + (lane & 8) * 2;

    for (int c = 0; c < 32; c++) {
        if (c == 31) cp_wait0(); else cp_wait1();
        __syncthreads();
        const uint32_t st = sb + (c & 1) * G_STAGE;
        #pragma unroll
        for (int kk = 0; kk < 2; kk++) {
            uint32_t ah[4][4], al[4][4], bf[4][2];
            #pragma unroll
            for (int mi = 0; mi < 4; mi++) {
                const uint32_t ad = st + S_AH + a_l + mi * 16 * GRS + kk * 32;
                ldsm4(ah[mi], ad);
                ldsm4(al[mi], ad + (S_AL - S_AH));
            }
            #pragma unroll
            for (int np = 0; np < 2; np++) {
                uint32_t t[4];
                ldsm4(t, st + S_WH + b_l + np * 16 * GRS + kk * 32);
                bf[np * 2][0] = t[0]; bf[np * 2][1] = t[1];
                bf[np * 2 + 1][0] = t[2]; bf[np * 2 + 1][1] = t[3];
            }
            #pragma unroll
            for (int mi = 0; mi < 4; mi++)
                #pragma unroll
                for (int ni = 0; ni < 4; ni++) {
                    mma_f16(acc[mi][ni], ah[mi], bf[ni]);
                    mma_f16(acc[mi][ni], al[mi], bf[ni]);
                }
        }
        __syncthreads();
        if (c + 2 < 32) g_load(sb, Ah, Al, Wg, m0, n0, c + 2, tid);
    }
}

// -------- QKV projection: z selects q/k/v; writes fp16 per-head -------------
__global__ __launch_bounds__(256, 2) void qkv_gemm(const float* __restrict__ bias)
{
    extern __shared__ char sm[];
    const int z = blockIdx.z;
    const __half* Ah = g_inh + (size_t)z * NELEM;
    const __half* Al = g_inl + (size_t)z * NELEM;
    const __half* Wg = g_wih + (size_t)z * EMB * DM;
    const float* bz = bias + z * EMB;

    const int m0 = blockIdx.y * 128;
    const int n0 = blockIdx.x * 128;

    float acc[4][4][4];
    gemm_core(Ah, Al, Wg, m0, n0, su32(sm), acc);

    const int lane = threadIdx.x & 31, wid = threadIdx.x >> 5;
    const int mh = wid & 1, nq = wid >> 1;
    const int g = lane >> 2, t4 = lane & 3;

    __half* dst = (z == 0) ? g_qh : (z == 1) ? g_kh : g_vh;
    const float sc = (z == 0) ? 0.125f : 1.0f;

    #pragma unroll
    for (int mi = 0; mi < 4; mi++) {
        #pragma unroll
        for (int ni = 0; ni < 4; ni++) {
            const int mrow = m0 + mh * 64 + mi * 16 + g;
            const int ncol = n0 + nq * 32 + ni * 8 + t4 * 2;
            const float b0 = __ldg(&bz[ncol]), b1 = __ldg(&bz[ncol + 1]);
            const int h = ncol >> 6, d = ncol & 63;
            #pragma unroll
            for (int rr = 0; rr < 2; rr++) {
                const int m = mrow + rr * 8;
                const int t = m >> 1, b = m & 1;
                const float v0 = (acc[mi][ni][rr * 2 + 0] + b0) * sc;
                const float v1 = (acc[mi][ni][rr * 2 + 1] + b1) * sc;
                const size_t idx = ((size_t)(b * NH + h) * T_LEN + t) * HD + d;
                *(uint32_t*)(dst + idx) = fpk(v0, v1);
            }
        }
    }
}

// -------- Output projection: C = attn(fp16 hi/lo) @ Wo^T + bo ---------------
__global__ __launch_bounds__(256, 2) void out_gemm(const float* __restrict__ bias,
                                                   float* __restrict__ C)
{
    extern __shared__ char sm[];
    const int m0 = blockIdx.y * 128;
    const int n0 = blockIdx.x * 128;

    float acc[4][4][4];
    gemm_core(g_ah, g_al, g_woh, m0, n0, su32(sm), acc);

    const int lane = threadIdx.x & 31, wid = threadIdx.x >> 5;
    const int mh = wid & 1, nq = wid >> 1;
    const int g = lane >> 2, t4 = lane & 3;

    #pragma unroll
    for (int mi = 0; mi < 4; mi++) {
        #pragma unroll
        for (int ni = 0; ni < 4; ni++) {
            const int mrow = m0 + mh * 64 + mi * 16 + g;
            const int ncol = n0 + nq * 32 + ni * 8 + t4 * 2;
            const float b0 = __ldg(&bias[ncol]), b1 = __ldg(&bias[ncol + 1]);
            #pragma unroll
            for (int rr = 0; rr < 2; rr++) {
                const int m = mrow + rr * 8;
                float2 v;
                v.x = acc[mi][ni][rr * 2 + 0] + b0;
                v.y = acc[mi][ni][rr * 2 + 1] + b1;
                *(float2*)(C + (size_t)m * DM + ncol) = v;
            }
        }
    }
}

// ============================================================================
// Flash attention, single fp16 mma. CTA = 128 q-rows x one (b,h), 8 warps x
// 16 q-rows. Q staged once; K/V 64-key tiles cp.async double-buffered.
// q pre-scaled by 1/8; mask applied only if g_mask_nz.
// ============================================================================
#define ARS 144
#define F_Q  0
#define F_KV 18432
#define F_KVS 18432          // per stage: K 9216 + V 9216
#define F_SMEM (F_KV + 2 * F_KVS)   // 55296

__device__ __forceinline__ void f_stage_kv(uint32_t sb, size_t hbase, int it, int tid)
{
    const uint32_t st = sb + F_KV + (it & 1) * F_KVS;
    const int s0 = it * 64;
    #pragma unroll
    for (int i = 0; i < 2; i++) {
        const int idx = tid + i * 256;
        const int row = idx >> 3, cc = idx & 7;
        const size_t src = (hbase + s0 + row) * HD + cc * 8;
        cpa(st + row * ARS + cc * 16, g_kh + src);
        cpa(st + 9216 + row * ARS + cc * 16, g_vh + src);
    }
    cp_commit();
}

__global__ __launch_bounds__(256, 2) void flash_mma(const float* __restrict__ mask)
{
    extern __shared__ char sm[];
    const uint32_t sb = su32(sm);
    const int tid = threadIdx.x, lane = tid & 31, w = tid >> 5;
    const int bh = blockIdx.y, qt = blockIdx.x;
    const int g = lane >> 2, t4 = lane & 3;
    const size_t hbase = (size_t)bh * T_LEN;
    const int mnz = g_mask_nz;

    {   // stage Q (single fp16)
        const size_t qb = (hbase + qt * 128) * HD;
        #pragma unroll
        for (int i = 0; i < 4; i++) {
            const int idx = tid + i * 256;      // 0..1023
            const int row = idx >> 3, cc = idx & 7;
            cpa(sb + F_Q + row * ARS + cc * 16, g_qh + qb + (size_t)row * HD + cc * 8);
        }
        cp_commit();
    }
    f_stage_kv(sb, hbase, 0, tid);
    f_stage_kv(sb, hbase, 1, tid);
    cp_wait2();
    __syncthreads();

    uint32_t qf[4][4];
    #pragma unroll
    for (int j = 0; j < 4; j++)
        ldsm4(qf[j], sb + F_Q + (w * 16 + (lane & 15)) * ARS +
                     (j * 16 + ((lane >> 4) << 3)) * 2);

    float oacc[8][4];
    #pragma unroll
    for (int i = 0; i < 8; i++)
        #pragma unroll
        for (int v = 0; v < 4; v++) oacc[i][v] = 0.f;
    float m0r = -1e30f, m1r = -1e30f, l0 = 0.f, l1 = 0.f;

    const int tq = qt * 128 + w * 16 + g;
    const float* mr0 = mask + (size_t)tq * T_LEN;
    const float* mr1 = mr0 + (size_t)8 * T_LEN;

    #pragma unroll 1
    for (int it = 0; it < 32; it++) {
        if (it == 31) cp_wait0(); else cp_wait1();
        __syncthreads();
        const uint32_t kst = sb + F_KV + (it & 1) * F_KVS;
        const uint32_t vst = kst + 9216;

        // ---- S = Q K^T (single fp16; q pre-scaled) ----
        float sacc[8][4];
        #pragma unroll
        for (int i = 0; i < 8; i++)
            #pragma unroll
            for (int v = 0; v < 4; v++) sacc[i][v] = 0.f;

        #pragma unroll
        for (int j = 0; j < 4; j++) {
            uint32_t kb[8][2];
            #pragma unroll
            for (int np = 0; np < 4; np++) {
                uint32_t t[4];
                ldsm4(t, kst + (np * 16 + ((lane >> 4) << 3) + (lane & 7)) * ARS +
                         (j * 16 + (lane & 8)) * 2);
                kb[np * 2][0] = t[0]; kb[np * 2][1] = t[1];
                kb[np * 2 + 1][0] = t[2]; kb[np * 2 + 1][1] = t[3];
            }
            #pragma unroll
            for (int jn = 0; jn < 8; jn++)
                mma_f16(sacc[jn], qf[j], kb[jn]);
        }

        // ---- optional mask + online softmax ----
        const int s0 = it * 64;
        if (mnz) {
            #pragma unroll
            for (int jn = 0; jn < 8; jn++) {
                const int sc = s0 + jn * 8 + t4 * 2;
                float2 ma = *(const float2*)(mr0 + sc);
                float2 mb = *(const float2*)(mr1 + sc);
                sacc[jn][0] += ma.x; sacc[jn][1] += ma.y;
                sacc[jn][2] += mb.x; sacc[jn][3] += mb.y;
            }
        }
        float mx0 = -1e30f, mx1 = -1e30f;
        #pragma unroll
        for (int jn = 0; jn < 8; jn++) {
            mx0 = fmaxf(mx0, fmaxf(sacc[jn][0], sacc[jn][1]));
            mx1 = fmaxf(mx1, fmaxf(sacc[jn][2], sacc[jn][3]));
        }
        mx0 = fmaxf(mx0, __shfl_xor_sync(0xffffffffu, mx0, 1));
        mx0 = fmaxf(mx0, __shfl_xor_sync(0xffffffffu, mx0, 2));
        mx1 = fmaxf(mx1, __shfl_xor_sync(0xffffffffu, mx1, 1));
        mx1 = fmaxf(mx1, __shfl_xor_sync(0xffffffffu, mx1, 2));

        const float mn0 = fmaxf(m0r, mx0), mn1 = fmaxf(m1r, mx1);
        const float c0 = __expf(m0r - mn0), c1 = __expf(m1r - mn1);
        m0r = mn0; m1r = mn1;
        l0 *= c0; l1 *= c1;
        #pragma unroll
        for (int jd = 0; jd < 8; jd++) {
            oacc[jd][0] *= c0; oacc[jd][1] *= c0;
            oacc[jd][2] *= c1; oacc[jd][3] *= c1;
        }
        #pragma unroll
        for (int jn = 0; jn < 8; jn++) {
            sacc[jn][0] = __expf(sacc[jn][0] - mn0);
            sacc[jn][1] = __expf(sacc[jn][1] - mn0);
            sacc[jn][2] = __expf(sacc[jn][2] - mn1);
            sacc[jn][3] = __expf(sacc[jn][3] - mn1);
            l0 += sacc[jn][0] + sacc[jn][1];
            l1 += sacc[jn][2] + sacc[jn][3];
        }

        // ---- O += P V (single fp16 p) ----
        #pragma unroll
        for (int js = 0; js < 4; js++) {
            uint32_t pf[4];
            pf[0] = fpk(sacc[2 * js][0], sacc[2 * js][1]);
            pf[1] = fpk(sacc[2 * js][2], sacc[2 * js][3]);
            pf[2] = fpk(sacc[2 * js + 1][0], sacc[2 * js + 1][1]);
            pf[3] = fpk(sacc[2 * js + 1][2], sacc[2 * js + 1][3]);

            uint32_t vb[8][2];
            #pragma unroll
            for (int dp = 0; dp < 4; dp++) {
                uint32_t t[4];
                ldsm4t(t, vst + (js * 16 + (lane & 15)) * ARS +
                          (dp * 16 + ((lane >> 4) << 3)) * 2);
                vb[dp * 2][0] = t[0]; vb[dp * 2][1] = t[1];
                vb[dp * 2 + 1][0] = t[2]; vb[dp * 2 + 1][1] = t[3];
            }
            #pragma unroll
            for (int jd = 0; jd < 8; jd++)
                mma_f16(oacc[jd], pf, vb[jd]);
        }
        __syncthreads();
        if (it + 2 < 32) f_stage_kv(sb, hbase, it + 2, tid);
    }

    l0 += __shfl_xor_sync(0xffffffffu, l0, 1);
    l0 += __shfl_xor_sync(0xffffffffu, l0, 2);
    l1 += __shfl_xor_sync(0xffffffffu, l1, 1);
    l1 += __shfl_xor_sync(0xffffffffu, l1, 2);
    const float i0 = 1.0f / l0, i1 = 1.0f / l1;

    const int b = bh >> 4, h = bh & 15;
    const size_t r0 = ((size_t)tq * BSZ + b) * EMB + h * HD;
    const size_t r1 = ((size_t)(tq + 8) * BSZ + b) * EMB + h * HD;
    #pragma unroll
    for (int jd = 0; jd < 8; jd++) {
        const int d = jd * 8 + t4 * 2;
        uint32_t H, L;
        fspl_pair(oacc[jd][0] * i0, oacc[jd][1] * i0, H, L);
        *(uint32_t*)(g_ah + r0 + d) = H;
        *(uint32_t*)(g_al + r0 + d) = L;
        fspl_pair(oacc[jd][2] * i1, oacc[jd][3] * i1, H, L);
        *(uint32_t*)(g_ah + r1 + d) = H;
        *(uint32_t*)(g_al + r1 + d) = L;
    }
}

// ============================================================================
// Launch
// ============================================================================
extern "C" void kernel_launch(void* const* d_in, const int* in_sizes, int n_in,
                              void* d_out, int out_size)
{
    const float* query  = (const float*)d_in[0];
    const float* key    = (const float*)d_in[1];
    const float* value  = (const float*)d_in[2];
    const float* mask   = (const float*)d_in[3];
    const float* in_w   = (const float*)d_in[4];
    const float* in_b   = (const float*)d_in[5];
    const float* out_w  = (const float*)d_in[6];
    const float* out_b  = (const float*)d_in[7];
    float* out = (float*)d_out;

    cudaFuncSetAttribute(qkv_gemm, cudaFuncAttributeMaxDynamicSharedMemorySize, G_SMEM);
    cudaFuncSetAttribute(out_gemm, cudaFuncAttributeMaxDynamicSharedMemorySize, G_SMEM);
    cudaFuncSetAttribute(flash_mma, cudaFuncAttributeMaxDynamicSharedMemorySize, F_SMEM);

    // 0) prep: split inputs; convert weights; scan mask for nonzeros
    prep_split<<<dim3(NELEM / 1024, 3), 256>>>(query, key, value);
    mask_scan<<<(T_LEN * T_LEN) / 1024, 256>>>(mask);
    prep_cvt<<<(3 * EMB * DM) / 1024, 256>>>(in_w, 0, 3 * EMB * DM);
    prep_cvt<<<(DM * EMB) / 1024, 256>>>(out_w, 1, DM * EMB);

    // 1) QKV projection (fp16 x2 mma, 128x128 tiles)
    qkv_gemm<<<dim3(EMB / 128, MROWS / 128, 3), 256, G_SMEM>>>(in_b);

    // 2) Attention (single-fp16 mma flash, mask fast-path)
    flash_mma<<<dim3(T_LEN / 128, BSZ * NH), 256, F_SMEM>>>(mask);

    // 3) Output projection (fp16 x2 mma) -> d_out
    out_gemm<<<dim3(DM / 128, MROWS / 128), 256, G_SMEM>>>(out_b, out);
}

// round 8
// speedup vs baseline: 8.1567x; 1.3560x over previous
#include <cuda_runtime.h>
#include <cuda_fp16.h>
#include <cstdint>

#define T_LEN 2048
#define BSZ   2
#define DM    1024
#define NH    16
#define HD    64
#define EMB   1024
#define MROWS 4096
#define NELEM ((size_t)MROWS * DM)          // 4M elements per input tensor

// ---------------- scratch (allocation-free: device globals) ----------------
__device__ __half g_in[3 * NELEM];          // inputs fp16 (q,k,v)
__device__ __half g_wih[(size_t)3 * EMB * DM];  // in_proj_weight fp16
__device__ __half g_woh[(size_t)DM * EMB];      // out_proj_weight fp16
__device__ __half g_qh[(size_t)BSZ * NH * T_LEN * HD];  // q fp16 (pre-scaled 1/8)
__device__ __half g_kh[(size_t)BSZ * NH * T_LEN * HD];  // k fp16
__device__ __half g_vh[(size_t)BSZ * NH * T_LEN * HD];  // v fp16
__device__ __half g_ah[NELEM];              // attn out fp16  [t*B+b][e]
__device__ int g_mask_nz;                   // 1 if mask has any nonzero

// ============================ PTX helpers ===================================
__device__ __forceinline__ uint32_t su32(const void* p) {
    uint32_t a;
    asm("{ .reg .u64 t; cvta.to.shared.u64 t, %1; cvt.u32.u64 %0, t; }"
        : "=r"(a) : "l"(p));
    return a;
}
__device__ __forceinline__ void cpa(uint32_t s, const void* g) {
    asm volatile("cp.async.cg.shared.global [%0], [%1], 16;" :: "r"(s), "l"(g));
}
__device__ __forceinline__ void cp_commit() {
    asm volatile("cp.async.commit_group;" ::: "memory");
}
__device__ __forceinline__ void cp_wait0() {
    asm volatile("cp.async.wait_group 0;" ::: "memory");
}
__device__ __forceinline__ void cp_wait1() {
    asm volatile("cp.async.wait_group 1;" ::: "memory");
}
__device__ __forceinline__ void cp_wait2() {
    asm volatile("cp.async.wait_group 2;" ::: "memory");
}
__device__ __forceinline__ void ldsm4(uint32_t r[4], uint32_t a) {
    asm volatile("ldmatrix.sync.aligned.m8n8.x4.shared.b16 {%0,%1,%2,%3}, [%4];"
                 : "=r"(r[0]), "=r"(r[1]), "=r"(r[2]), "=r"(r[3]) : "r"(a));
}
__device__ __forceinline__ void ldsm4t(uint32_t r[4], uint32_t a) {
    asm volatile("ldmatrix.sync.aligned.m8n8.x4.trans.shared.b16 {%0,%1,%2,%3}, [%4];"
                 : "=r"(r[0]), "=r"(r[1]), "=r"(r[2]), "=r"(r[3]) : "r"(a));
}
__device__ __forceinline__ void mma_f16(float c[4], const uint32_t a[4],
                                        const uint32_t b[2]) {
    asm volatile(
        "mma.sync.aligned.m16n8k16.row.col.f32.f16.f16.f32 "
        "{%0,%1,%2,%3}, {%4,%5,%6,%7}, {%8,%9}, {%0,%1,%2,%3};"
        : "+f"(c[0]), "+f"(c[1]), "+f"(c[2]), "+f"(c[3])
        : "r"(a[0]), "r"(a[1]), "r"(a[2]), "r"(a[3]), "r"(b[0]), "r"(b[1]));
}

__device__ __forceinline__ uint32_t fpk(float a, float b) {
    __half2 t = __floats2half2_rn(a, b);
    return *reinterpret_cast<uint32_t*>(&t);
}

// ============================================================================
// Prep kernels
// ============================================================================
__global__ __launch_bounds__(256) void prep_cvt_in(
    const float* __restrict__ q, const float* __restrict__ k,
    const float* __restrict__ v)
{
    if (blockIdx.x == 0 && blockIdx.y == 0 && threadIdx.x == 0) g_mask_nz = 0;
    const int z = blockIdx.y;
    const float* s = (z == 0) ? q : (z == 1) ? k : v;
    __half* d = g_in + (size_t)z * NELEM;
    const size_t i = ((size_t)blockIdx.x * 256 + threadIdx.x) * 4;
    float4 x = *(const float4*)(s + i);
    uint2 H;
    H.x = fpk(x.x, x.y);
    H.y = fpk(x.z, x.w);
    *(uint2*)(d + i) = H;
}

__global__ __launch_bounds__(256) void prep_cvt_w(const float* __restrict__ s,
                                                  int which, int n)
{
    __half* d = which ? g_woh : g_wih;
    const int i = (blockIdx.x * 256 + threadIdx.x) * 4;
    if (i < n) {
        float4 x = *(const float4*)(s + i);
        uint2 H;
        H.x = fpk(x.x, x.y);
        H.y = fpk(x.z, x.w);
        *(uint2*)(d + i) = H;
    }
}

__global__ __launch_bounds__(256) void mask_scan(const float* __restrict__ m)
{
    const size_t i = ((size_t)blockIdx.x * 256 + threadIdx.x) * 4;
    float4 v = *(const float4*)(m + i);
    if (v.x != 0.f || v.y != 0.f || v.z != 0.f || v.w != 0.f) g_mask_nz = 1;
}

// ============================================================================
// GEMM core (TN, single fp16): CTA 128x128, chunk K=32, cp.async dbl-buffered.
// smem/stage: A[128x32] W[128x32] fp16, row stride 80B (conflict-free).
// 8 warps = 2(m) x 4(n); warp tile 64x32 -> acc[4][4][4].
// ============================================================================
#define GRS 80
#define S_A 0
#define S_W 10240
#define G_STAGE 20480
#define G_SMEM (2 * G_STAGE)

__device__ __forceinline__ void g_load(uint32_t sb, const __half* A,
                                       const __half* Wg,
                                       int m0, int n0, int c, int tid)
{
    const uint32_t st = sb + (c & 1) * G_STAGE;
    const int k0 = c * 32;
    #pragma unroll
    for (int i = 0; i < 2; i++) {
        const int idx = tid + i * 256;          // 0..511
        const int row = idx >> 2, cc = idx & 3;
        const uint32_t o = row * GRS + cc * 16;
        cpa(st + S_A + o, A  + (size_t)(m0 + row) * DM + k0 + cc * 8);
        cpa(st + S_W + o, Wg + (size_t)(n0 + row) * DM + k0 + cc * 8);
    }
    cp_commit();
}

__device__ __forceinline__ void gemm_core(
    const __half* __restrict__ A, const __half* __restrict__ Wg,
    int m0, int n0, uint32_t sb, float (&acc)[4][4][4])
{
    const int tid = threadIdx.x, lane = tid & 31, wid = tid >> 5;
    const int mh = wid & 1;          // 0..1 : 64-row half
    const int nq = wid >> 1;         // 0..3 : 32-col quad

    #pragma unroll
    for (int i = 0; i < 4; i++)
        #pragma unroll
        for (int j = 0; j < 4; j++)
            #pragma unroll
            for (int v = 0; v < 4; v++) acc[i][j][v] = 0.f;

    g_load(sb, A, Wg, m0, n0, 0, tid);
    g_load(sb, A, Wg, m0, n0, 1, tid);

    const int a_l = (mh * 64 + (lane & 15)) * GRS + ((lane >> 4) << 3) * 2;
    const int b_l = (nq * 32 + ((lane >> 4) << 3) + (lane & 7)) * GRS + (lane & 8) * 2;

    for (int c = 0; c < 32; c++) {
        if (c == 31) cp_wait0(); else cp_wait1();
        __syncthreads();
        const uint32_t st = sb + (c & 1) * G_STAGE;
        #pragma unroll
        for (int kk = 0; kk < 2; kk++) {
            uint32_t af[4][4], bf[4][2];
            #pragma unroll
            for (int mi = 0; mi < 4; mi++)
                ldsm4(af[mi], st + S_A + a_l + mi * 16 * GRS + kk * 32);
            #pragma unroll
            for (int np = 0; np < 2; np++) {
                uint32_t t[4];
                ldsm4(t, st + S_W + b_l + np * 16 * GRS + kk * 32);
                bf[np * 2][0] = t[0]; bf[np * 2][1] = t[1];
                bf[np * 2 + 1][0] = t[2]; bf[np * 2 + 1][1] = t[3];
            }
            #pragma unroll
            for (int mi = 0; mi < 4; mi++)
                #pragma unroll
                for (int ni = 0; ni < 4; ni++)
                    mma_f16(acc[mi][ni], af[mi], bf[ni]);
        }
        __syncthreads();
        if (c + 2 < 32) g_load(sb, A, Wg, m0, n0, c + 2, tid);
    }
}

// -------- QKV projection: z selects q/k/v; writes fp16 per-head -------------
__global__ __launch_bounds__(256, 2) void qkv_gemm(const float* __restrict__ bias)
{
    extern __shared__ char sm[];
    const int z = blockIdx.z;
    const __half* A  = g_in + (size_t)z * NELEM;
    const __half* Wg = g_wih + (size_t)z * EMB * DM;
    const float* bz = bias + z * EMB;

    const int m0 = blockIdx.y * 128;
    const int n0 = blockIdx.x * 128;

    float acc[4][4][4];
    gemm_core(A, Wg, m0, n0, su32(sm), acc);

    const int lane = threadIdx.x & 31, wid = threadIdx.x >> 5;
    const int mh = wid & 1, nq = wid >> 1;
    const int g = lane >> 2, t4 = lane & 3;

    __half* dst = (z == 0) ? g_qh : (z == 1) ? g_kh : g_vh;
    const float sc = (z == 0) ? 0.125f : 1.0f;

    #pragma unroll
    for (int mi = 0; mi < 4; mi++) {
        #pragma unroll
        for (int ni = 0; ni < 4; ni++) {
            const int mrow = m0 + mh * 64 + mi * 16 + g;
            const int ncol = n0 + nq * 32 + ni * 8 + t4 * 2;
            const float b0 = __ldg(&bz[ncol]), b1 = __ldg(&bz[ncol + 1]);
            const int h = ncol >> 6, d = ncol & 63;
            #pragma unroll
            for (int rr = 0; rr < 2; rr++) {
                const int m = mrow + rr * 8;
                const int t = m >> 1, b = m & 1;
                const float v0 = (acc[mi][ni][rr * 2 + 0] + b0) * sc;
                const float v1 = (acc[mi][ni][rr * 2 + 1] + b1) * sc;
                const size_t idx = ((size_t)(b * NH + h) * T_LEN + t) * HD + d;
                *(uint32_t*)(dst + idx) = fpk(v0, v1);
            }
        }
    }
}

// -------- Output projection: C = attn(fp16) @ Wo^T + bo ---------------------
__global__ __launch_bounds__(256, 2) void out_gemm(const float* __restrict__ bias,
                                                   float* __restrict__ C)
{
    extern __shared__ char sm[];
    const int m0 = blockIdx.y * 128;
    const int n0 = blockIdx.x * 128;

    float acc[4][4][4];
    gemm_core(g_ah, g_woh, m0, n0, su32(sm), acc);

    const int lane = threadIdx.x & 31, wid = threadIdx.x >> 5;
    const int mh = wid & 1, nq = wid >> 1;
    const int g = lane >> 2, t4 = lane & 3;

    #pragma unroll
    for (int mi = 0; mi < 4; mi++) {
        #pragma unroll
        for (int ni = 0; ni < 4; ni++) {
            const int mrow = m0 + mh * 64 + mi * 16 + g;
            const int ncol = n0 + nq * 32 + ni * 8 + t4 * 2;
            const float b0 = __ldg(&bias[ncol]), b1 = __ldg(&bias[ncol + 1]);
            #pragma unroll
            for (int rr = 0; rr < 2; rr++) {
                const int m = mrow + rr * 8;
                float2 v;
                v.x = acc[mi][ni][rr * 2 + 0] + b0;
                v.y = acc[mi][ni][rr * 2 + 1] + b1;
                *(float2*)(C + (size_t)m * DM + ncol) = v;
            }
        }
    }
}

// ============================================================================
// Flash attention, single fp16 mma. CTA = 128 q-rows x one (b,h), 8 warps x
// 16 q-rows. Q staged once; K/V 64-key tiles cp.async double-buffered.
// q pre-scaled by 1/8; mask applied only if g_mask_nz.
// ============================================================================
#define ARS 144
#define F_Q  0
#define F_KV 18432
#define F_KVS 18432          // per stage: K 9216 + V 9216
#define F_SMEM (F_KV + 2 * F_KVS)   // 55296

__device__ __forceinline__ void f_stage_kv(uint32_t sb, size_t hbase, int it, int tid)
{
    const uint32_t st = sb + F_KV + (it & 1) * F_KVS;
    const int s0 = it * 64;
    #pragma unroll
    for (int i = 0; i < 2; i++) {
        const int idx = tid + i * 256;
        const int row = idx >> 3, cc = idx & 7;
        const size_t src = (hbase + s0 + row) * HD + cc * 8;
        cpa(st + row * ARS + cc * 16, g_kh + src);
        cpa(st + 9216 + row * ARS + cc * 16, g_vh + src);
    }
    cp_commit();
}

__global__ __launch_bounds__(256, 2) void flash_mma(const float* __restrict__ mask)
{
    extern __shared__ char sm[];
    const uint32_t sb = su32(sm);
    const int tid = threadIdx.x, lane = tid & 31, w = tid >> 5;
    const int bh = blockIdx.y, qt = blockIdx.x;
    const int g = lane >> 2, t4 = lane & 3;
    const size_t hbase = (size_t)bh * T_LEN;
    const int mnz = g_mask_nz;

    {   // stage Q
        const size_t qb = (hbase + qt * 128) * HD;
        #pragma unroll
        for (int i = 0; i < 4; i++) {
            const int idx = tid + i * 256;      // 0..1023
            const int row = idx >> 3, cc = idx & 7;
            cpa(sb + F_Q + row * ARS + cc * 16, g_qh + qb + (size_t)row * HD + cc * 8);
        }
        cp_commit();
    }
    f_stage_kv(sb, hbase, 0, tid);
    f_stage_kv(sb, hbase, 1, tid);
    cp_wait2();
    __syncthreads();

    uint32_t qf[4][4];
    #pragma unroll
    for (int j = 0; j < 4; j++)
        ldsm4(qf[j], sb + F_Q + (w * 16 + (lane & 15)) * ARS +
                     (j * 16 + ((lane >> 4) << 3)) * 2);

    float oacc[8][4];
    #pragma unroll
    for (int i = 0; i < 8; i++)
        #pragma unroll
        for (int v = 0; v < 4; v++) oacc[i][v] = 0.f;
    float m0r = -1e30f, m1r = -1e30f, l0 = 0.f, l1 = 0.f;

    const int tq = qt * 128 + w * 16 + g;
    const float* mr0 = mask + (size_t)tq * T_LEN;
    const float* mr1 = mr0 + (size_t)8 * T_LEN;

    #pragma unroll 1
    for (int it = 0; it < 32; it++) {
        if (it == 31) cp_wait0(); else cp_wait1();
        __syncthreads();
        const uint32_t kst = sb + F_KV + (it & 1) * F_KVS;
        const uint32_t vst = kst + 9216;

        // ---- S = Q K^T ----
        float sacc[8][4];
        #pragma unroll
        for (int i = 0; i < 8; i++)
            #pragma unroll
            for (int v = 0; v < 4; v++) sacc[i][v] = 0.f;

        #pragma unroll
        for (int j = 0; j < 4; j++) {
            uint32_t kb[8][2];
            #pragma unroll
            for (int np = 0; np < 4; np++) {
                uint32_t t[4];
                ldsm4(t, kst + (np * 16 + ((lane >> 4) << 3) + (lane & 7)) * ARS +
                         (j * 16 + (lane & 8)) * 2);
                kb[np * 2][0] = t[0]; kb[np * 2][1] = t[1];
                kb[np * 2 + 1][0] = t[2]; kb[np * 2 + 1][1] = t[3];
            }
            #pragma unroll
            for (int jn = 0; jn < 8; jn++)
                mma_f16(sacc[jn], qf[j], kb[jn]);
        }

        // ---- optional mask + online softmax ----
        const int s0 = it * 64;
        if (mnz) {
            #pragma unroll
            for (int jn = 0; jn < 8; jn++) {
                const int sc = s0 + jn * 8 + t4 * 2;
                float2 ma = *(const float2*)(mr0 + sc);
                float2 mb = *(const float2*)(mr1 + sc);
                sacc[jn][0] += ma.x; sacc[jn][1] += ma.y;
                sacc[jn][2] += mb.x; sacc[jn][3] += mb.y;
            }
        }
        float mx0 = -1e30f, mx1 = -1e30f;
        #pragma unroll
        for (int jn = 0; jn < 8; jn++) {
            mx0 = fmaxf(mx0, fmaxf(sacc[jn][0], sacc[jn][1]));
            mx1 = fmaxf(mx1, fmaxf(sacc[jn][2], sacc[jn][3]));
        }
        mx0 = fmaxf(mx0, __shfl_xor_sync(0xffffffffu, mx0, 1));
        mx0 = fmaxf(mx0, __shfl_xor_sync(0xffffffffu, mx0, 2));
        mx1 = fmaxf(mx1, __shfl_xor_sync(0xffffffffu, mx1, 1));
        mx1 = fmaxf(mx1, __shfl_xor_sync(0xffffffffu, mx1, 2));

        const float mn0 = fmaxf(m0r, mx0), mn1 = fmaxf(m1r, mx1);
        const float c0 = __expf(m0r - mn0), c1 = __expf(m1r - mn1);
        m0r = mn0; m1r = mn1;
        l0 *= c0; l1 *= c1;
        #pragma unroll
        for (int jd = 0; jd < 8; jd++) {
            oacc[jd][0] *= c0; oacc[jd][1] *= c0;
            oacc[jd][2] *= c1; oacc[jd][3] *= c1;
        }
        #pragma unroll
        for (int jn = 0; jn < 8; jn++) {
            sacc[jn][0] = __expf(sacc[jn][0] - mn0);
            sacc[jn][1] = __expf(sacc[jn][1] - mn0);
            sacc[jn][2] = __expf(sacc[jn][2] - mn1);
            sacc[jn][3] = __expf(sacc[jn][3] - mn1);
            l0 += sacc[jn][0] + sacc[jn][1];
            l1 += sacc[jn][2] + sacc[jn][3];
        }

        // ---- O += P V ----
        #pragma unroll
        for (int js = 0; js < 4; js++) {
            uint32_t pf[4];
            pf[0] = fpk(sacc[2 * js][0], sacc[2 * js][1]);
            pf[1] = fpk(sacc[2 * js][2], sacc[2 * js][3]);
            pf[2] = fpk(sacc[2 * js + 1][0], sacc[2 * js + 1][1]);
            pf[3] = fpk(sacc[2 * js + 1][2], sacc[2 * js + 1][3]);

            uint32_t vb[8][2];
            #pragma unroll
            for (int dp = 0; dp < 4; dp++) {
                uint32_t t[4];
                ldsm4t(t, vst + (js * 16 + (lane & 15)) * ARS +
                          (dp * 16 + ((lane >> 4) << 3)) * 2);
                vb[dp * 2][0] = t[0]; vb[dp * 2][1] = t[1];
                vb[dp * 2 + 1][0] = t[2]; vb[dp * 2 + 1][1] = t[3];
            }
            #pragma unroll
            for (int jd = 0; jd < 8; jd++)
                mma_f16(oacc[jd], pf, vb[jd]);
        }
        __syncthreads();
        if (it + 2 < 32) f_stage_kv(sb, hbase, it + 2, tid);
    }

    l0 += __shfl_xor_sync(0xffffffffu, l0, 1);
    l0 += __shfl_xor_sync(0xffffffffu, l0, 2);
    l1 += __shfl_xor_sync(0xffffffffu, l1, 1);
    l1 += __shfl_xor_sync(0xffffffffu, l1, 2);
    const float i0 = 1.0f / l0, i1 = 1.0f / l1;

    const int b = bh >> 4, h = bh & 15;
    const size_t r0 = ((size_t)tq * BSZ + b) * EMB + h * HD;
    const size_t r1 = ((size_t)(tq + 8) * BSZ + b) * EMB + h * HD;
    #pragma unroll
    for (int jd = 0; jd < 8; jd++) {
        const int d = jd * 8 + t4 * 2;
        *(uint32_t*)(g_ah + r0 + d) = fpk(oacc[jd][0] * i0, oacc[jd][1] * i0);
        *(uint32_t*)(g_ah + r1 + d) = fpk(oacc[jd][2] * i1, oacc[jd][3] * i1);
    }
}

// ============================================================================
// Launch
// ============================================================================
extern "C" void kernel_launch(void* const* d_in, const int* in_sizes, int n_in,
                              void* d_out, int out_size)
{
    const float* query  = (const float*)d_in[0];
    const float* key    = (const float*)d_in[1];
    const float* value  = (const float*)d_in[2];
    const float* mask   = (const float*)d_in[3];
    const float* in_w   = (const float*)d_in[4];
    const float* in_b   = (const float*)d_in[5];
    const float* out_w  = (const float*)d_in[6];
    const float* out_b  = (const float*)d_in[7];
    float* out = (float*)d_out;

    cudaFuncSetAttribute(qkv_gemm, cudaFuncAttributeMaxDynamicSharedMemorySize, G_SMEM);
    cudaFuncSetAttribute(out_gemm, cudaFuncAttributeMaxDynamicSharedMemorySize, G_SMEM);
    cudaFuncSetAttribute(flash_mma, cudaFuncAttributeMaxDynamicSharedMemorySize, F_SMEM);

    // 0) prep: convert inputs + weights to fp16; scan mask for nonzeros
    prep_cvt_in<<<dim3(NELEM / 1024, 3), 256>>>(query, key, value);
    mask_scan<<<(T_LEN * T_LEN) / 1024, 256>>>(mask);
    prep_cvt_w<<<(3 * EMB * DM) / 1024, 256>>>(in_w, 0, 3 * EMB * DM);
    prep_cvt_w<<<(DM * EMB) / 1024, 256>>>(out_w, 1, DM * EMB);

    // 1) QKV projection (single fp16 mma, 128x128 tiles)
    qkv_gemm<<<dim3(EMB / 128, MROWS / 128, 3), 256, G_SMEM>>>(in_b);

    // 2) Attention (single fp16 mma flash, mask fast-path)
    flash_mma<<<dim3(T_LEN / 128, BSZ * NH), 256, F_SMEM>>>(mask);

    // 3) Output projection (single fp16 mma) -> d_out
    out_gemm<<<dim3(DM / 128, MROWS / 128), 256, G_SMEM>>>(out_b, out);
}